// round 1
// baseline (speedup 1.0000x reference)
#include <cuda_runtime.h>
#include <math.h>

#define BB 32
#define TT 128
#define VV 32000
#define EE 300
#define HH 512
#define G4 (4*HH)      // 2048
#define MM (BB*TT)     // 4096
#define LOGITS_ELEMS ((long long)MM * VV)   // 131072000

// ---- scratch (device globals: allocation-free) ----
__device__ float g_x[MM * EE];        // gathered embeddings  [4096, 300]
__device__ float g_xz[MM * G4];       // x @ W_x + b          [4096, 2048]
__device__ float g_h[2][HH * BB];     // hidden ping-pong, [H][B] (k-major)
__device__ float g_c[HH * BB];        // cell, [H][B]
__device__ float g_hs[MM * HH];       // all hidden states    [4096, 512]

// ---------------------------------------------------------------------------
// embedding gather: g_x[m][e] = emb[inputs[m]][e]
// ---------------------------------------------------------------------------
__global__ void gather_kernel(const int* __restrict__ inputs,
                              const float* __restrict__ emb) {
    int i = blockIdx.x * blockDim.x + threadIdx.x;
    if (i < MM * EE) {
        int m = i / EE;
        int e = i - m * EE;
        g_x[i] = emb[(long long)inputs[m] * EE + e];
    }
}

// ---------------------------------------------------------------------------
// init: transpose hidden/cell [B,H] -> [H,B]
// ---------------------------------------------------------------------------
__global__ void init_state_kernel(const float* __restrict__ hidden,
                                  const float* __restrict__ cell) {
    int i = blockIdx.x * blockDim.x + threadIdx.x;
    if (i < BB * HH) {
        int b = i / HH;
        int u = i - b * HH;
        g_h[0][u * BB + b] = hidden[i];
        g_c[u * BB + b]    = cell[i];
    }
}

// ---------------------------------------------------------------------------
// Generic SGEMM + bias: C[M,N] = A[M,K] @ B[K,N] + bias[N]
// BM=BN=128, BK=8, TM=TN=8, 256 threads. M,N must divide tiles; K arbitrary.
// ---------------------------------------------------------------------------
template<int BM, int BN, int BK, int TM, int TN>
__global__ void __launch_bounds__(256, 2)
sgemm_bias_kernel(const float* __restrict__ A, const float* __restrict__ Bm,
                  const float* __restrict__ bias, float* __restrict__ C,
                  int M, int N, int K) {
    __shared__ float As[BK][BM];
    __shared__ float Bs[BK][BN];
    const int tid  = threadIdx.x;
    const int brow = blockIdx.y * BM;
    const int bcol = blockIdx.x * BN;
    const int tx = tid % (BN / TN);   // 0..15
    const int ty = tid / (BN / TN);   // 0..15

    float acc[TM][TN];
#pragma unroll
    for (int i = 0; i < TM; i++)
#pragma unroll
        for (int j = 0; j < TN; j++) acc[i][j] = 0.f;

    for (int k0 = 0; k0 < K; k0 += BK) {
        // load A tile (BM x BK)
#pragma unroll
        for (int i = 0; i < BM * BK / 256; i++) {
            int idx = tid + i * 256;
            int r = idx / BK, c = idx % BK;
            As[c][r] = (k0 + c < K) ? A[(long long)(brow + r) * K + k0 + c] : 0.f;
        }
        // load B tile (BK x BN)
#pragma unroll
        for (int i = 0; i < BK * BN / 256; i++) {
            int idx = tid + i * 256;
            int r = idx / BN, c = idx % BN;
            Bs[r][c] = (k0 + r < K) ? Bm[(long long)(k0 + r) * N + bcol + c] : 0.f;
        }
        __syncthreads();
#pragma unroll
        for (int k = 0; k < BK; k++) {
            float ra[TM], rb[TN];
#pragma unroll
            for (int i = 0; i < TM; i++) ra[i] = As[k][ty * TM + i];
#pragma unroll
            for (int j = 0; j < TN; j++) rb[j] = Bs[k][tx * TN + j];
#pragma unroll
            for (int i = 0; i < TM; i++)
#pragma unroll
                for (int j = 0; j < TN; j++) acc[i][j] += ra[i] * rb[j];
        }
        __syncthreads();
    }
#pragma unroll
    for (int i = 0; i < TM; i++) {
        long long row = brow + ty * TM + i;
#pragma unroll
        for (int j = 0; j < TN; j++) {
            int col = bcol + tx * TN + j;
            C[row * N + col] = acc[i][j] + bias[col];
        }
    }
}

// ---------------------------------------------------------------------------
// One LSTM step. grid = 128 blocks (4 units each), 128 threads.
// Thread (b = tid%32, c0 = tid/32) computes all 4 gates for unit u0+c0, batch b.
// h state layout [H][B] for coalesced loads. Writes hs [M,H] for output GEMM.
// ---------------------------------------------------------------------------
__global__ void __launch_bounds__(128, 8)
lstm_step_kernel(const float* __restrict__ Wh, int t) {
    __shared__ float sh_h[64 * 32];   // [k][b]
    __shared__ float sh_w[64][16];    // [k][c0*4 + gate]
    const int tid = threadIdx.x;
    const int b  = tid & 31;
    const int c0 = tid >> 5;          // 0..3
    const int u0 = blockIdx.x * 4;
    const int u  = u0 + c0;

    const float* __restrict__ h_in = g_h[t & 1];
    float* __restrict__ h_out      = g_h[(t + 1) & 1];

    float acc0 = 0.f, acc1 = 0.f, acc2 = 0.f, acc3 = 0.f;

    for (int kc = 0; kc < HH; kc += 64) {
#pragma unroll
        for (int i = 0; i < 16; i++) {
            int idx = tid + i * 128;           // 0..2047  -> (k, b)
            sh_h[idx] = h_in[kc * BB + idx];
        }
#pragma unroll
        for (int i = 0; i < 8; i++) {
            int idx = tid + i * 128;           // 0..1023
            int k  = idx >> 4;
            int q  = idx & 15;
            int cc = q >> 2;
            int g  = q & 3;
            sh_w[k][q] = Wh[(long long)(kc + k) * G4 + g * HH + u0 + cc];
        }
        __syncthreads();
#pragma unroll
        for (int k = 0; k < 64; k++) {
            float hv = sh_h[k * 32 + b];
            float4 w = *(const float4*)&sh_w[k][c0 * 4];
            acc0 += hv * w.x;
            acc1 += hv * w.y;
            acc2 += hv * w.z;
            acc3 += hv * w.w;
        }
        __syncthreads();
    }

    const float* xzr = g_xz + (long long)(b * TT + t) * G4;
    float zi = acc0 + xzr[0 * HH + u];
    float zf = acc1 + xzr[1 * HH + u];
    float zg = acc2 + xzr[2 * HH + u];
    float zo = acc3 + xzr[3 * HH + u];

    float si = 1.f / (1.f + expf(-zi));
    float sf = 1.f / (1.f + expf(-zf));
    float so = 1.f / (1.f + expf(-zo));
    float cn = sf * g_c[u * BB + b] + si * tanhf(zg);
    float hn = so * tanhf(cn);

    g_c[u * BB + b]   = cn;
    h_out[u * BB + b] = hn;
    g_hs[(long long)(b * TT + t) * HH + u] = hn;
}

// ---------------------------------------------------------------------------
// final: h_last/c_last -> d_out tail ([B,H] row-major), transposing from [H,B]
// after 128 steps, final h lives in g_h[0] (128 is even).
// ---------------------------------------------------------------------------
__global__ void finalize_kernel(float* __restrict__ out) {
    int i = blockIdx.x * blockDim.x + threadIdx.x;
    if (i < BB * HH) {
        int b = i / HH;
        int u = i - b * HH;
        out[LOGITS_ELEMS + i]           = g_h[0][u * BB + b];
        out[LOGITS_ELEMS + BB * HH + i] = g_c[u * BB + b];
    }
}

// ---------------------------------------------------------------------------
extern "C" void kernel_launch(void* const* d_in, const int* in_sizes, int n_in,
                              void* d_out, int out_size) {
    const int*   inputs = (const int*)  d_in[0];
    const float* hidden = (const float*)d_in[1];
    const float* cell   = (const float*)d_in[2];
    const float* emb    = (const float*)d_in[3];
    const float* Wx     = (const float*)d_in[4];
    const float* Wh     = (const float*)d_in[5];
    const float* bias   = (const float*)d_in[6];
    const float* Wout   = (const float*)d_in[7];
    const float* bout   = (const float*)d_in[8];
    float* out = (float*)d_out;

    float *px, *pxz, *phs;
    cudaGetSymbolAddress((void**)&px,  g_x);
    cudaGetSymbolAddress((void**)&pxz, g_xz);
    cudaGetSymbolAddress((void**)&phs, g_hs);

    // 1. embedding gather
    gather_kernel<<<(MM * EE + 255) / 256, 256>>>(inputs, emb);

    // 2. init recurrent state
    init_state_kernel<<<(BB * HH + 255) / 256, 256>>>(hidden, cell);

    // 3. xz = x @ W_x + b   (4096 x 2048 x 300)
    {
        dim3 grid(G4 / 128, MM / 128);
        sgemm_bias_kernel<128,128,8,8,8><<<grid, 256>>>(px, Wx, bias, pxz,
                                                        MM, G4, EE);
    }

    // 4. 128 sequential LSTM steps
    for (int t = 0; t < TT; t++) {
        lstm_step_kernel<<<HH / 4, 128>>>(Wh, t);
    }

    // 5. logits = hs @ W_out + b_out   (4096 x 32000 x 512)
    {
        dim3 grid(VV / 128, MM / 128);
        sgemm_bias_kernel<128,128,8,8,8><<<grid, 256>>>(phs, Wout, bout, out,
                                                        MM, VV, HH);
    }

    // 6. h_last / c_last
    finalize_kernel<<<(BB * HH + 255) / 256, 256>>>(out);
}

// round 3
// speedup vs baseline: 1.6834x; 1.6834x over previous
#include <cuda_runtime.h>
#include <cuda_bf16.h>
#include <math.h>
#include <cstdint>

#define BB 32
#define TT 128
#define VV 32000
#define EE 300
#define HH 512
#define G4 (4*HH)      // 2048
#define MM (BB*TT)     // 4096
#define LOGITS_ELEMS ((long long)MM * VV)   // 131072000

// split-bf16 GEMM dims
#define GKK 1536       // 3 * 512 stacked K

// HMMA output-GEMM tiling
#define OBM 128
#define OBN 256
#define OBK 32
#define OSTAGES 3
#define OTHREADS 512
#define A_ST_BYTES (128*80)                  // rows padded to 40 halves (80B)
#define B_ST_BYTES (256*80)
#define STAGE_BYTES (A_ST_BYTES + B_ST_BYTES)   // 30720
#define OSMEM (OSTAGES*STAGE_BYTES)             // 92160

// ---- scratch (device globals: allocation-free) ----
__device__ float g_x[MM * EE];        // gathered embeddings  [4096, 300]
__device__ float g_xz[MM * G4];       // x @ W_x + b          [4096, 2048]
__device__ float g_h[2][HH * BB];     // hidden ping-pong, [H][B] (k-major)
__device__ float g_c[HH * BB];        // cell, [H][B]
__device__ float g_hs[MM * HH];       // all hidden states    [4096, 512]
__device__ __nv_bfloat16 g_A[(long long)MM * GKK];   // [4096,1536]  = [Ah|Al|Ah]
__device__ __nv_bfloat16 g_B[(long long)VV * GKK];   // [32000,1536] = [Bh|Bh|Bl] (K-major)

// ===========================================================================
__device__ __forceinline__ uint32_t smem_u32(const void* p) {
    uint32_t a;
    asm("{ .reg .u64 t; cvta.to.shared.u64 t, %1; cvt.u32.u64 %0, t; }" : "=r"(a) : "l"(p));
    return a;
}
__device__ __forceinline__ void cp_async16(uint32_t s, const void* g) {
    asm volatile("cp.async.cg.shared.global [%0], [%1], 16;" :: "r"(s), "l"(g));
}

// ---------------------------------------------------------------------------
// embedding gather
// ---------------------------------------------------------------------------
__global__ void gather_kernel(const int* __restrict__ inputs,
                              const float* __restrict__ emb) {
    int i = blockIdx.x * blockDim.x + threadIdx.x;
    if (i < MM * EE) {
        int m = i / EE;
        int e = i - m * EE;
        g_x[i] = emb[(long long)inputs[m] * EE + e];
    }
}

// ---------------------------------------------------------------------------
// init: transpose hidden/cell [B,H] -> [H,B]
// ---------------------------------------------------------------------------
__global__ void init_state_kernel(const float* __restrict__ hidden,
                                  const float* __restrict__ cell) {
    int i = blockIdx.x * blockDim.x + threadIdx.x;
    if (i < BB * HH) {
        int b = i / HH;
        int u = i - b * HH;
        g_h[0][u * BB + b] = hidden[i];
        g_c[u * BB + b]    = cell[i];
    }
}

// ---------------------------------------------------------------------------
// fp32 SGEMM + bias (xz = x @ W_x + b only)
// ---------------------------------------------------------------------------
template<int BM, int BN, int BK, int TM, int TN>
__global__ void __launch_bounds__(256, 2)
sgemm_bias_kernel(const float* __restrict__ A, const float* __restrict__ Bm,
                  const float* __restrict__ bias, float* __restrict__ C,
                  int M, int N, int K) {
    __shared__ float As[BK][BM];
    __shared__ float Bs[BK][BN];
    const int tid  = threadIdx.x;
    const int brow = blockIdx.y * BM;
    const int bcol = blockIdx.x * BN;
    const int tx = tid % (BN / TN);
    const int ty = tid / (BN / TN);

    float acc[TM][TN];
#pragma unroll
    for (int i = 0; i < TM; i++)
#pragma unroll
        for (int j = 0; j < TN; j++) acc[i][j] = 0.f;

    for (int k0 = 0; k0 < K; k0 += BK) {
#pragma unroll
        for (int i = 0; i < BM * BK / 256; i++) {
            int idx = tid + i * 256;
            int r = idx / BK, c = idx % BK;
            As[c][r] = (k0 + c < K) ? A[(long long)(brow + r) * K + k0 + c] : 0.f;
        }
#pragma unroll
        for (int i = 0; i < BK * BN / 256; i++) {
            int idx = tid + i * 256;
            int r = idx / BN, c = idx % BN;
            Bs[r][c] = (k0 + r < K) ? Bm[(long long)(k0 + r) * N + bcol + c] : 0.f;
        }
        __syncthreads();
#pragma unroll
        for (int k = 0; k < BK; k++) {
            float ra[TM], rb[TN];
#pragma unroll
            for (int i = 0; i < TM; i++) ra[i] = As[k][ty * TM + i];
#pragma unroll
            for (int j = 0; j < TN; j++) rb[j] = Bs[k][tx * TN + j];
#pragma unroll
            for (int i = 0; i < TM; i++)
#pragma unroll
                for (int j = 0; j < TN; j++) acc[i][j] += ra[i] * rb[j];
        }
        __syncthreads();
    }
#pragma unroll
    for (int i = 0; i < TM; i++) {
        long long row = brow + ty * TM + i;
#pragma unroll
        for (int j = 0; j < TN; j++) {
            int col = bcol + tx * TN + j;
            C[row * N + col] = acc[i][j] + bias[col];
        }
    }
}

// ---------------------------------------------------------------------------
// One LSTM step (unchanged this round)
// ---------------------------------------------------------------------------
__global__ void __launch_bounds__(128, 8)
lstm_step_kernel(const float* __restrict__ Wh, int t) {
    __shared__ float sh_h[64 * 32];
    __shared__ float sh_w[64][16];
    const int tid = threadIdx.x;
    const int b  = tid & 31;
    const int c0 = tid >> 5;
    const int u0 = blockIdx.x * 4;
    const int u  = u0 + c0;

    const float* __restrict__ h_in = g_h[t & 1];
    float* __restrict__ h_out      = g_h[(t + 1) & 1];

    float acc0 = 0.f, acc1 = 0.f, acc2 = 0.f, acc3 = 0.f;

    for (int kc = 0; kc < HH; kc += 64) {
#pragma unroll
        for (int i = 0; i < 16; i++) {
            int idx = tid + i * 128;
            sh_h[idx] = h_in[kc * BB + idx];
        }
#pragma unroll
        for (int i = 0; i < 8; i++) {
            int idx = tid + i * 128;
            int k  = idx >> 4;
            int q  = idx & 15;
            int cc = q >> 2;
            int g  = q & 3;
            sh_w[k][q] = Wh[(long long)(kc + k) * G4 + g * HH + u0 + cc];
        }
        __syncthreads();
#pragma unroll
        for (int k = 0; k < 64; k++) {
            float hv = sh_h[k * 32 + b];
            float4 w = *(const float4*)&sh_w[k][c0 * 4];
            acc0 += hv * w.x;
            acc1 += hv * w.y;
            acc2 += hv * w.z;
            acc3 += hv * w.w;
        }
        __syncthreads();
    }

    const float* xzr = g_xz + (long long)(b * TT + t) * G4;
    float zi = acc0 + xzr[0 * HH + u];
    float zf = acc1 + xzr[1 * HH + u];
    float zg = acc2 + xzr[2 * HH + u];
    float zo = acc3 + xzr[3 * HH + u];

    float si = 1.f / (1.f + expf(-zi));
    float sf = 1.f / (1.f + expf(-zf));
    float so = 1.f / (1.f + expf(-zo));
    float cn = sf * g_c[u * BB + b] + si * tanhf(zg);
    float hn = so * tanhf(cn);

    g_c[u * BB + b]   = cn;
    h_out[u * BB + b] = hn;
    g_hs[(long long)(b * TT + t) * HH + u] = hn;
}

// ---------------------------------------------------------------------------
// Split hs into A' = [Ah | Al | Ah]  (bf16, K-major rows of 1536)
// ---------------------------------------------------------------------------
__global__ void split_hs_kernel() {
    int i = blockIdx.x * blockDim.x + threadIdx.x;
    if (i < MM * HH) {
        int m = i >> 9;
        int k = i & 511;
        float v = g_hs[i];
        __nv_bfloat16 hi = __float2bfloat16(v);
        __nv_bfloat16 lo = __float2bfloat16(v - __bfloat162float(hi));
        long long base = (long long)m * GKK;
        g_A[base + k]        = hi;
        g_A[base + 512 + k]  = lo;
        g_A[base + 1024 + k] = hi;
    }
}

// ---------------------------------------------------------------------------
// Split + transpose W_out [512,32000] -> B' [32000,1536] = [Bh | Bh | Bl]
// ---------------------------------------------------------------------------
__global__ void split_wout_kernel(const float* __restrict__ W) {
    __shared__ float t[32][33];
    int n0 = blockIdx.x * 32, k0 = blockIdx.y * 32;
    int tx = threadIdx.x, ty = threadIdx.y;   // 32 x 8
#pragma unroll
    for (int i = 0; i < 4; i++) {
        int k = ty + i * 8;
        t[k][tx] = W[(long long)(k0 + k) * VV + n0 + tx];
    }
    __syncthreads();
#pragma unroll
    for (int i = 0; i < 4; i++) {
        int n = ty + i * 8;
        float v = t[tx][n];
        __nv_bfloat16 hi = __float2bfloat16(v);
        __nv_bfloat16 lo = __float2bfloat16(v - __bfloat162float(hi));
        long long base = (long long)(n0 + n) * GKK + k0;
        g_B[base + tx]        = hi;
        g_B[base + 512 + tx]  = hi;
        g_B[base + 1024 + tx] = lo;
    }
}

// ---------------------------------------------------------------------------
// HMMA bf16 GEMM: C[4096,32000] = A'[4096,1536] @ B'[32000,1536]^T + bout
// CTA 128x256, BK=32, 512 thr (4x4 warps, warp tile 32x64), 3-stage cp.async.
// ---------------------------------------------------------------------------
__global__ void __launch_bounds__(OTHREADS, 1)
out_gemm_hmma(const __nv_bfloat16* __restrict__ A, const __nv_bfloat16* __restrict__ B,
              const float* __restrict__ bout, float* __restrict__ C) {
    extern __shared__ char smem[];
    const int tid  = threadIdx.x;
    const int lane = tid & 31;
    const int wid  = tid >> 5;
    const int wm   = wid & 3;          // 0..3  -> m offset wm*32
    const int wn   = wid >> 2;         // 0..3  -> n offset wn*64
    const int m0 = blockIdx.x * OBM;
    const int n0 = blockIdx.y * OBN;
    const uint32_t sbase = smem_u32(smem);

    auto load_stage = [&](int s, int kt) {
        uint32_t sA = sbase + s * STAGE_BYTES;
        uint32_t sB = sA + A_ST_BYTES;
        long long k0 = (long long)kt * OBK;
        {   // A tile: 128 rows x 32 halves = 512 x 16B chunks
            int r = tid >> 2, ch = tid & 3;
            cp_async16(sA + r * 80 + ch * 16,
                       A + (long long)(m0 + r) * GKK + k0 + ch * 8);
        }
#pragma unroll
        for (int i = 0; i < 2; i++) {   // B tile: 256 rows -> 1024 chunks
            int idx = tid + i * 512;
            int r = idx >> 2, ch = idx & 3;
            cp_async16(sB + r * 80 + ch * 16,
                       B + (long long)(n0 + r) * GKK + k0 + ch * 8);
        }
        asm volatile("cp.async.commit_group;" ::: "memory");
    };

    float acc[2][8][4];
#pragma unroll
    for (int i = 0; i < 2; i++)
#pragma unroll
        for (int j = 0; j < 8; j++)
#pragma unroll
            for (int q = 0; q < 4; q++) acc[i][j][q] = 0.f;

    const int KT = GKK / OBK;   // 48
#pragma unroll
    for (int s = 0; s < OSTAGES - 1; s++) load_stage(s, s);

    for (int kt = 0; kt < KT; kt++) {
        asm volatile("cp.async.wait_group %0;" :: "n"(OSTAGES - 2));
        __syncthreads();
        if (kt + OSTAGES - 1 < KT)
            load_stage((kt + OSTAGES - 1) % OSTAGES, kt + OSTAGES - 1);

        uint32_t sA = sbase + (kt % OSTAGES) * STAGE_BYTES;
        uint32_t sB = sA + A_ST_BYTES;
        const int krow = lane & 15;
#pragma unroll
        for (int ks = 0; ks < 2; ks++) {
            const int kcolb = (ks * 16 + (lane >> 4) * 8) * 2;   // byte offset in row
            uint32_t a[2][4], bb[4][4];
#pragma unroll
            for (int mt = 0; mt < 2; mt++) {
                uint32_t addr = sA + (wm * 32 + mt * 16 + krow) * 80 + kcolb;
                asm volatile("ldmatrix.sync.aligned.m8n8.x4.shared.b16 {%0,%1,%2,%3}, [%4];"
                    : "=r"(a[mt][0]), "=r"(a[mt][1]), "=r"(a[mt][2]), "=r"(a[mt][3])
                    : "r"(addr));
            }
#pragma unroll
            for (int np = 0; np < 4; np++) {
                uint32_t addr = sB + (wn * 64 + np * 16 + krow) * 80 + kcolb;
                asm volatile("ldmatrix.sync.aligned.m8n8.x4.shared.b16 {%0,%1,%2,%3}, [%4];"
                    : "=r"(bb[np][0]), "=r"(bb[np][1]), "=r"(bb[np][2]), "=r"(bb[np][3])
                    : "r"(addr));
            }
#pragma unroll
            for (int mt = 0; mt < 2; mt++)
#pragma unroll
                for (int nt = 0; nt < 8; nt++) {
                    uint32_t b0 = bb[nt >> 1][nt & 1];
                    uint32_t b1 = bb[nt >> 1][(nt & 1) + 2];
                    asm volatile(
                        "mma.sync.aligned.m16n8k16.row.col.f32.bf16.bf16.f32 "
                        "{%0,%1,%2,%3}, {%4,%5,%6,%7}, {%8,%9}, {%0,%1,%2,%3};"
                        : "+f"(acc[mt][nt][0]), "+f"(acc[mt][nt][1]),
                          "+f"(acc[mt][nt][2]), "+f"(acc[mt][nt][3])
                        : "r"(a[mt][0]), "r"(a[mt][1]), "r"(a[mt][2]), "r"(a[mt][3]),
                          "r"(b0), "r"(b1));
                }
        }
    }

    // epilogue: direct STG with bias
    const int row_b = m0 + wm * 32 + (lane >> 2);
    const int col_b = n0 + wn * 64 + (lane & 3) * 2;
#pragma unroll
    for (int nt = 0; nt < 8; nt++) {
        int col = col_b + nt * 8;
        float b0v = __ldg(bout + col);
        float b1v = __ldg(bout + col + 1);
#pragma unroll
        for (int mt = 0; mt < 2; mt++) {
            long long r0 = row_b + mt * 16;
            float2 v0 = make_float2(acc[mt][nt][0] + b0v, acc[mt][nt][1] + b1v);
            float2 v1 = make_float2(acc[mt][nt][2] + b0v, acc[mt][nt][3] + b1v);
            *(float2*)&C[r0 * VV + col]       = v0;
            *(float2*)&C[(r0 + 8) * VV + col] = v1;
        }
    }
}

// ---------------------------------------------------------------------------
// final: h_last/c_last -> d_out tail
// ---------------------------------------------------------------------------
__global__ void finalize_kernel(float* __restrict__ out) {
    int i = blockIdx.x * blockDim.x + threadIdx.x;
    if (i < BB * HH) {
        int b = i / HH;
        int u = i - b * HH;
        out[LOGITS_ELEMS + i]           = g_h[0][u * BB + b];
        out[LOGITS_ELEMS + BB * HH + i] = g_c[u * BB + b];
    }
}

// ---------------------------------------------------------------------------
extern "C" void kernel_launch(void* const* d_in, const int* in_sizes, int n_in,
                              void* d_out, int out_size) {
    const int*   inputs = (const int*)  d_in[0];
    const float* hidden = (const float*)d_in[1];
    const float* cell   = (const float*)d_in[2];
    const float* emb    = (const float*)d_in[3];
    const float* Wx     = (const float*)d_in[4];
    const float* Wh     = (const float*)d_in[5];
    const float* bias   = (const float*)d_in[6];
    const float* Wout   = (const float*)d_in[7];
    const float* bout   = (const float*)d_in[8];
    float* out = (float*)d_out;

    float *px, *pxz;
    __nv_bfloat16 *pA, *pB;
    cudaGetSymbolAddress((void**)&px,  g_x);
    cudaGetSymbolAddress((void**)&pxz, g_xz);
    cudaGetSymbolAddress((void**)&pA,  g_A);
    cudaGetSymbolAddress((void**)&pB,  g_B);

    cudaFuncSetAttribute(out_gemm_hmma,
                         cudaFuncAttributeMaxDynamicSharedMemorySize, OSMEM);

    // 1. embedding gather
    gather_kernel<<<(MM * EE + 255) / 256, 256>>>(inputs, emb);

    // 2. init recurrent state
    init_state_kernel<<<(BB * HH + 255) / 256, 256>>>(hidden, cell);

    // 3. xz = x @ W_x + b   (4096 x 2048 x 300)  fp32
    {
        dim3 grid(G4 / 128, MM / 128);
        sgemm_bias_kernel<128,128,8,8,8><<<grid, 256>>>(px, Wx, bias, pxz,
                                                        MM, G4, EE);
    }

    // 4. split W_out (independent of LSTM; do it early)
    {
        dim3 grid(VV / 32, HH / 32);
        split_wout_kernel<<<grid, dim3(32, 8)>>>(Wout);
    }

    // 5. 128 sequential LSTM steps
    for (int t = 0; t < TT; t++) {
        lstm_step_kernel<<<HH / 4, 128>>>(Wh, t);
    }

    // 6. split hs into A'
    split_hs_kernel<<<(MM * HH + 255) / 256, 256>>>();

    // 7. logits = A' @ B'^T + b_out  (HMMA bf16 split GEMM)
    {
        dim3 grid(MM / OBM, VV / OBN);   // (32, 125); x = m for L2 reuse of B
        out_gemm_hmma<<<grid, OTHREADS, OSMEM>>>(pA, pB, bout, out);
    }

    // 8. h_last / c_last
    finalize_kernel<<<(BB * HH + 255) / 256, 256>>>(out);
}

// round 4
// speedup vs baseline: 1.7780x; 1.0562x over previous
#include <cuda_runtime.h>
#include <cuda_bf16.h>
#include <math.h>
#include <cstdint>

#define BB 32
#define TT 128
#define VV 32000
#define EE 300
#define HH 512
#define G4 (4*HH)      // 2048
#define MM (BB*TT)     // 4096
#define LOGITS_ELEMS ((long long)MM * VV)   // 131072000

// split-bf16 GEMM dims
#define GKK 1536       // 3 * 512 stacked K

// HMMA output-GEMM tiling
#define OBM 128
#define OBN 256
#define OBK 32
#define OSTAGES 3
#define OTHREADS 512
#define A_ST_BYTES (128*80)
#define B_ST_BYTES (256*80)
#define STAGE_BYTES (A_ST_BYTES + B_ST_BYTES)   // 30720
#define OSMEM (OSTAGES*STAGE_BYTES)             // 92160

// persistent LSTM
#define NCTA 128
// dynamic smem float offsets
#define LW_OFF 0                       // 8 x 1028 = 8224
#define LH_OFF 8224                    // 2 x 32 x 132 = 8448
#define LZ_OFF (LH_OFF + 8448)         // 16 x 33 = 528
#define LC_OFF (LZ_OFF + 528)          // 128
#define LSMEM_FLOATS (LC_OFF + 128)
#define LSMEM_BYTES (LSMEM_FLOATS * 4) // 69,424 B

// ---- scratch (device globals: allocation-free) ----
__device__ float g_x[MM * EE];        // gathered embeddings  [4096, 300]
__device__ float g_xz[MM * G4];       // x @ W_x + b          [4096, 2048]
__device__ float g_hp[2][BB * HH];    // h ping-pong, [b][u] layout
__device__ __nv_bfloat16 g_A[(long long)MM * GKK];   // [4096,1536]  = [Ah|Al|Ah]
__device__ __nv_bfloat16 g_B[(long long)VV * GKK];   // [32000,1536] = [Bh|Bh|Bl]
__device__ unsigned g_bar_cnt = 0;
__device__ unsigned g_bar_gen = 0;

// ===========================================================================
__device__ __forceinline__ uint32_t smem_u32(const void* p) {
    uint32_t a;
    asm("{ .reg .u64 t; cvta.to.shared.u64 t, %1; cvt.u32.u64 %0, t; }" : "=r"(a) : "l"(p));
    return a;
}
__device__ __forceinline__ void cp_async16(uint32_t s, const void* g) {
    asm volatile("cp.async.cg.shared.global [%0], [%1], 16;" :: "r"(s), "l"(g));
}

// ---------------------------------------------------------------------------
// embedding gather
// ---------------------------------------------------------------------------
__global__ void gather_kernel(const int* __restrict__ inputs,
                              const float* __restrict__ emb) {
    int i = blockIdx.x * blockDim.x + threadIdx.x;
    if (i < MM * EE) {
        int m = i / EE;
        int e = i - m * EE;
        g_x[i] = emb[(long long)inputs[m] * EE + e];
    }
}

// ---------------------------------------------------------------------------
// fp32 SGEMM + bias (xz = x @ W_x + b only)
// ---------------------------------------------------------------------------
template<int BM, int BN, int BK, int TM, int TN>
__global__ void __launch_bounds__(256, 2)
sgemm_bias_kernel(const float* __restrict__ A, const float* __restrict__ Bm,
                  const float* __restrict__ bias, float* __restrict__ C,
                  int M, int N, int K) {
    __shared__ float As[BK][BM];
    __shared__ float Bs[BK][BN];
    const int tid  = threadIdx.x;
    const int brow = blockIdx.y * BM;
    const int bcol = blockIdx.x * BN;
    const int tx = tid % (BN / TN);
    const int ty = tid / (BN / TN);

    float acc[TM][TN];
#pragma unroll
    for (int i = 0; i < TM; i++)
#pragma unroll
        for (int j = 0; j < TN; j++) acc[i][j] = 0.f;

    for (int k0 = 0; k0 < K; k0 += BK) {
#pragma unroll
        for (int i = 0; i < BM * BK / 256; i++) {
            int idx = tid + i * 256;
            int r = idx / BK, c = idx % BK;
            As[c][r] = (k0 + c < K) ? A[(long long)(brow + r) * K + k0 + c] : 0.f;
        }
#pragma unroll
        for (int i = 0; i < BK * BN / 256; i++) {
            int idx = tid + i * 256;
            int r = idx / BN, c = idx % BN;
            Bs[r][c] = (k0 + r < K) ? Bm[(long long)(k0 + r) * N + bcol + c] : 0.f;
        }
        __syncthreads();
#pragma unroll
        for (int k = 0; k < BK; k++) {
            float ra[TM], rb[TN];
#pragma unroll
            for (int i = 0; i < TM; i++) ra[i] = As[k][ty * TM + i];
#pragma unroll
            for (int j = 0; j < TN; j++) rb[j] = Bs[k][tx * TN + j];
#pragma unroll
            for (int i = 0; i < TM; i++)
#pragma unroll
                for (int j = 0; j < TN; j++) acc[i][j] += ra[i] * rb[j];
        }
        __syncthreads();
    }
#pragma unroll
    for (int i = 0; i < TM; i++) {
        long long row = brow + ty * TM + i;
#pragma unroll
        for (int j = 0; j < TN; j++) {
            int col = bcol + tx * TN + j;
            C[row * N + col] = acc[i][j] + bias[col];
        }
    }
}

// ---------------------------------------------------------------------------
// Persistent LSTM: all 128 steps in one launch, 128 co-resident CTAs.
// CTA c owns units [4c, 4c+4) x 4 gates = 16 output columns.
// Wh slice (512 x 16 = 32KB) cached in smem for the whole kernel.
// Thread (b = tid&31, p = tid>>5) computes cols {2p, 2p+1}.
// ---------------------------------------------------------------------------
__global__ void __launch_bounds__(256, 1)
lstm_persistent(const float* __restrict__ Wh, const float* __restrict__ hidden,
                const float* __restrict__ cell, float* __restrict__ out) {
    extern __shared__ float sm[];
    float* sw = sm + LW_OFF;           // [8][1028]
    float* sh = sm + LH_OFF;           // [2][32][132]
    float* sz = sm + LZ_OFF;           // [16][33]
    float* sc = sm + LC_OFF;           // [128]
    const uint32_t sbase = smem_u32(sm);
    const int tid = threadIdx.x;
    const int b   = tid & 31;
    const int p   = tid >> 5;          // 0..7
    const int u0  = blockIdx.x * 4;

    __shared__ unsigned s_gen0;
    if (tid == 0) s_gen0 = *(volatile unsigned*)&g_bar_gen;

    // one-time: load Wh slice (cols g*512 + u0+uu) -> sw[p][2k+j]
#pragma unroll
    for (int it = 0; it < 8; it++) {
        int e = tid + it * 256;        // 0..2047
        int k = e >> 2, g = e & 3;
        float4 v = *(const float4*)&Wh[(long long)k * G4 + g * HH + u0];
        sw[(2 * g)     * 1028 + 2 * k    ] = v.x;
        sw[(2 * g)     * 1028 + 2 * k + 1] = v.y;
        sw[(2 * g + 1) * 1028 + 2 * k    ] = v.z;
        sw[(2 * g + 1) * 1028 + 2 * k + 1] = v.w;
    }
    if (tid < 128) {
        sc[tid] = cell[(tid & 31) * HH + u0 + (tid >> 5)];
    }
    __syncthreads();
    const unsigned gen0 = s_gen0;

    for (int t = 0; t < TT; t++) {
        const float* __restrict__ hsrc = (t == 0) ? hidden : g_hp[t & 1];
        float* __restrict__ hdst = g_hp[(t + 1) & 1];

        // chunked h load with cp.async double buffer (4 chunks of 128 k)
        auto issue = [&](int cc) {
            int buf = cc & 1;
#pragma unroll
            for (int it = 0; it < 4; it++) {
                int e = tid + it * 256;       // 0..1023
                int bb = e >> 5, seg = e & 31;
                cp_async16(sbase + (LH_OFF + buf * 4224 + bb * 132 + seg * 4) * 4,
                           hsrc + bb * HH + cc * 128 + seg * 4);
            }
            asm volatile("cp.async.commit_group;" ::: "memory");
        };
        issue(0);

        float acc0 = 0.f, acc1 = 0.f;
#pragma unroll 1
        for (int cc = 0; cc < 4; cc++) {
            if (cc < 3) {
                issue(cc + 1);
                asm volatile("cp.async.wait_group 1;" ::: "memory");
            } else {
                asm volatile("cp.async.wait_group 0;" ::: "memory");
            }
            __syncthreads();
            const float* hb = sh + (cc & 1) * 4224 + b * 132;
            const float* wb = sw + p * 1028 + cc * 256;
#pragma unroll
            for (int kk = 0; kk < 128; kk += 4) {
                float4 h4 = *(const float4*)&hb[kk];
                float4 w0 = *(const float4*)&wb[2 * kk];
                float4 w1 = *(const float4*)&wb[2 * kk + 4];
                acc0 += h4.x * w0.x; acc1 += h4.x * w0.y;
                acc0 += h4.y * w0.z; acc1 += h4.y * w0.w;
                acc0 += h4.z * w1.x; acc1 += h4.z * w1.y;
                acc0 += h4.w * w1.z; acc1 += h4.w * w1.w;
            }
            __syncthreads();
        }
        sz[(2 * p)     * 33 + b] = acc0;
        sz[(2 * p + 1) * 33 + b] = acc1;
        __syncthreads();

        // nonlinearity + writes (128 threads: 32 b x 4 units)
        if (tid < 128) {
            int bb = tid & 31, uu = tid >> 5;
            const float* xzr = g_xz + (long long)(bb * TT + t) * G4 + u0 + uu;
            float zi = sz[(0 + uu) * 33 + bb]  + xzr[0 * HH];
            float zf = sz[(4 + uu) * 33 + bb]  + xzr[1 * HH];
            float zg = sz[(8 + uu) * 33 + bb]  + xzr[2 * HH];
            float zo = sz[(12 + uu) * 33 + bb] + xzr[3 * HH];
            float si = 1.f / (1.f + expf(-zi));
            float sf = 1.f / (1.f + expf(-zf));
            float so = 1.f / (1.f + expf(-zo));
            float cn = sf * sc[tid] + si * tanhf(zg);
            float hn = so * tanhf(cn);
            sc[tid] = cn;
            hdst[bb * HH + u0 + uu] = hn;
            // bf16 split write straight into A' = [Ah | Al | Ah]
            __nv_bfloat16 hi = __float2bfloat16(hn);
            __nv_bfloat16 lo = __float2bfloat16(hn - __bfloat162float(hi));
            long long abase = (long long)(bb * TT + t) * GKK + u0 + uu;
            g_A[abase]        = hi;
            g_A[abase + 512]  = lo;
            g_A[abase + 1024] = hi;
            if (t == TT - 1)
                out[LOGITS_ELEMS + bb * HH + u0 + uu] = hn;
        }

        // grid barrier (sense via monotonically increasing generation)
        __syncthreads();
        if (tid == 0) {
            __threadfence();
            if (atomicAdd(&g_bar_cnt, 1u) == NCTA - 1) {
                *(volatile unsigned*)&g_bar_cnt = 0;
                __threadfence();
                atomicAdd(&g_bar_gen, 1u);
            } else {
                while (*(volatile unsigned*)&g_bar_gen - gen0 < (unsigned)(t + 1)) { }
            }
            __threadfence();
        }
        __syncthreads();
    }

    if (tid < 128) {
        out[LOGITS_ELEMS + BB * HH + (tid & 31) * HH + u0 + (tid >> 5)] = sc[tid];
    }
}

// ---------------------------------------------------------------------------
// Split + transpose W_out [512,32000] -> B' [32000,1536] = [Bh | Bh | Bl]
// ---------------------------------------------------------------------------
__global__ void split_wout_kernel(const float* __restrict__ W) {
    __shared__ float t[32][33];
    int n0 = blockIdx.x * 32, k0 = blockIdx.y * 32;
    int tx = threadIdx.x, ty = threadIdx.y;   // 32 x 8
#pragma unroll
    for (int i = 0; i < 4; i++) {
        int k = ty + i * 8;
        t[k][tx] = W[(long long)(k0 + k) * VV + n0 + tx];
    }
    __syncthreads();
#pragma unroll
    for (int i = 0; i < 4; i++) {
        int n = ty + i * 8;
        float v = t[tx][n];
        __nv_bfloat16 hi = __float2bfloat16(v);
        __nv_bfloat16 lo = __float2bfloat16(v - __bfloat162float(hi));
        long long base = (long long)(n0 + n) * GKK + k0;
        g_B[base + tx]        = hi;
        g_B[base + 512 + tx]  = hi;
        g_B[base + 1024 + tx] = lo;
    }
}

// ---------------------------------------------------------------------------
// HMMA bf16 GEMM: C[4096,32000] = A'[4096,1536] @ B'[32000,1536]^T + bout
// ---------------------------------------------------------------------------
__global__ void __launch_bounds__(OTHREADS, 1)
out_gemm_hmma(const __nv_bfloat16* __restrict__ A, const __nv_bfloat16* __restrict__ B,
              const float* __restrict__ bout, float* __restrict__ C) {
    extern __shared__ char smem[];
    const int tid  = threadIdx.x;
    const int lane = tid & 31;
    const int wid  = tid >> 5;
    const int wm   = wid & 3;
    const int wn   = wid >> 2;
    const int m0 = blockIdx.x * OBM;
    const int n0 = blockIdx.y * OBN;
    const uint32_t sbase = smem_u32(smem);

    auto load_stage = [&](int s, int kt) {
        uint32_t sA = sbase + s * STAGE_BYTES;
        uint32_t sB = sA + A_ST_BYTES;
        long long k0 = (long long)kt * OBK;
        {
            int r = tid >> 2, ch = tid & 3;
            cp_async16(sA + r * 80 + ch * 16,
                       A + (long long)(m0 + r) * GKK + k0 + ch * 8);
        }
#pragma unroll
        for (int i = 0; i < 2; i++) {
            int idx = tid + i * 512;
            int r = idx >> 2, ch = idx & 3;
            cp_async16(sB + r * 80 + ch * 16,
                       B + (long long)(n0 + r) * GKK + k0 + ch * 8);
        }
        asm volatile("cp.async.commit_group;" ::: "memory");
    };

    float acc[2][8][4];
#pragma unroll
    for (int i = 0; i < 2; i++)
#pragma unroll
        for (int j = 0; j < 8; j++)
#pragma unroll
            for (int q = 0; q < 4; q++) acc[i][j][q] = 0.f;

    const int KT = GKK / OBK;   // 48
#pragma unroll
    for (int s = 0; s < OSTAGES - 1; s++) load_stage(s, s);

    for (int kt = 0; kt < KT; kt++) {
        asm volatile("cp.async.wait_group %0;" :: "n"(OSTAGES - 2));
        __syncthreads();
        if (kt + OSTAGES - 1 < KT)
            load_stage((kt + OSTAGES - 1) % OSTAGES, kt + OSTAGES - 1);

        uint32_t sA = sbase + (kt % OSTAGES) * STAGE_BYTES;
        uint32_t sB = sA + A_ST_BYTES;
        const int krow = lane & 15;
#pragma unroll
        for (int ks = 0; ks < 2; ks++) {
            const int kcolb = (ks * 16 + (lane >> 4) * 8) * 2;
            uint32_t a[2][4], bb[4][4];
#pragma unroll
            for (int mt = 0; mt < 2; mt++) {
                uint32_t addr = sA + (wm * 32 + mt * 16 + krow) * 80 + kcolb;
                asm volatile("ldmatrix.sync.aligned.m8n8.x4.shared.b16 {%0,%1,%2,%3}, [%4];"
                    : "=r"(a[mt][0]), "=r"(a[mt][1]), "=r"(a[mt][2]), "=r"(a[mt][3])
                    : "r"(addr));
            }
#pragma unroll
            for (int np = 0; np < 4; np++) {
                uint32_t addr = sB + (wn * 64 + np * 16 + krow) * 80 + kcolb;
                asm volatile("ldmatrix.sync.aligned.m8n8.x4.shared.b16 {%0,%1,%2,%3}, [%4];"
                    : "=r"(bb[np][0]), "=r"(bb[np][1]), "=r"(bb[np][2]), "=r"(bb[np][3])
                    : "r"(addr));
            }
#pragma unroll
            for (int mt = 0; mt < 2; mt++)
#pragma unroll
                for (int nt = 0; nt < 8; nt++) {
                    uint32_t b0 = bb[nt >> 1][nt & 1];
                    uint32_t b1 = bb[nt >> 1][(nt & 1) + 2];
                    asm volatile(
                        "mma.sync.aligned.m16n8k16.row.col.f32.bf16.bf16.f32 "
                        "{%0,%1,%2,%3}, {%4,%5,%6,%7}, {%8,%9}, {%0,%1,%2,%3};"
                        : "+f"(acc[mt][nt][0]), "+f"(acc[mt][nt][1]),
                          "+f"(acc[mt][nt][2]), "+f"(acc[mt][nt][3])
                        : "r"(a[mt][0]), "r"(a[mt][1]), "r"(a[mt][2]), "r"(a[mt][3]),
                          "r"(b0), "r"(b1));
                }
        }
    }

    const int row_b = m0 + wm * 32 + (lane >> 2);
    const int col_b = n0 + wn * 64 + (lane & 3) * 2;
#pragma unroll
    for (int nt = 0; nt < 8; nt++) {
        int col = col_b + nt * 8;
        float b0v = __ldg(bout + col);
        float b1v = __ldg(bout + col + 1);
#pragma unroll
        for (int mt = 0; mt < 2; mt++) {
            long long r0 = row_b + mt * 16;
            float2 v0 = make_float2(acc[mt][nt][0] + b0v, acc[mt][nt][1] + b1v);
            float2 v1 = make_float2(acc[mt][nt][2] + b0v, acc[mt][nt][3] + b1v);
            *(float2*)&C[r0 * VV + col]       = v0;
            *(float2*)&C[(r0 + 8) * VV + col] = v1;
        }
    }
}

// ---------------------------------------------------------------------------
extern "C" void kernel_launch(void* const* d_in, const int* in_sizes, int n_in,
                              void* d_out, int out_size) {
    const int*   inputs = (const int*)  d_in[0];
    const float* hidden = (const float*)d_in[1];
    const float* cell   = (const float*)d_in[2];
    const float* emb    = (const float*)d_in[3];
    const float* Wx     = (const float*)d_in[4];
    const float* Wh     = (const float*)d_in[5];
    const float* bias   = (const float*)d_in[6];
    const float* Wout   = (const float*)d_in[7];
    const float* bout   = (const float*)d_in[8];
    float* out = (float*)d_out;

    float *px, *pxz;
    __nv_bfloat16 *pA, *pB;
    cudaGetSymbolAddress((void**)&px,  g_x);
    cudaGetSymbolAddress((void**)&pxz, g_xz);
    cudaGetSymbolAddress((void**)&pA,  g_A);
    cudaGetSymbolAddress((void**)&pB,  g_B);

    cudaFuncSetAttribute(out_gemm_hmma,
                         cudaFuncAttributeMaxDynamicSharedMemorySize, OSMEM);
    cudaFuncSetAttribute(lstm_persistent,
                         cudaFuncAttributeMaxDynamicSharedMemorySize, LSMEM_BYTES);

    // 1. embedding gather
    gather_kernel<<<(MM * EE + 255) / 256, 256>>>(inputs, emb);

    // 2. xz = x @ W_x + b   (4096 x 2048 x 300)  fp32
    {
        dim3 grid(G4 / 128, MM / 128);
        sgemm_bias_kernel<128,128,8,8,8><<<grid, 256>>>(px, Wx, bias, pxz,
                                                        MM, G4, EE);
    }

    // 3. split W_out (independent of LSTM)
    {
        dim3 grid(VV / 32, HH / 32);
        split_wout_kernel<<<grid, dim3(32, 8)>>>(Wout);
    }

    // 4. all 128 LSTM steps in ONE persistent launch
    //    (also writes A' split and h_last/c_last tail of d_out)
    lstm_persistent<<<NCTA, 256, LSMEM_BYTES>>>(Wh, hidden, cell, out);

    // 5. logits = A' @ B'^T + b_out  (HMMA bf16 split GEMM)
    {
        dim3 grid(MM / OBM, VV / OBN);
        out_gemm_hmma<<<grid, OTHREADS, OSMEM>>>(pA, pB, bout, out);
    }
}

// round 5
// speedup vs baseline: 1.9698x; 1.1078x over previous
#include <cuda_runtime.h>
#include <cuda_bf16.h>
#include <math.h>
#include <cstdint>

#define BB 32
#define TT 128
#define VV 32000
#define EE 300
#define HH 512
#define G4 (4*HH)      // 2048
#define MM (BB*TT)     // 4096
#define LOGITS_ELEMS ((long long)MM * VV)   // 131072000

// split-bf16 GEMM dims
#define GKK 1536       // 3 * 512 stacked K

// HMMA output-GEMM tiling
#define OBM 128
#define OBN 256
#define OBK 32
#define OSTAGES 3
#define OTHREADS 512
#define A_ST_BYTES (128*80)
#define B_ST_BYTES (256*80)
#define STAGE_BYTES (A_ST_BYTES + B_ST_BYTES)   // 30720
#define OSMEM (OSTAGES*STAGE_BYTES)             // 92160

// persistent LSTM (register-tiled)
#define NCTA 128
// dynamic smem float offsets
#define LW_OFF 0                        // [512][16]  = 8192
#define LH_OFF 8192                     // [512][32]  = 16384
#define LZ_OFF (LH_OFF + 16384)         // [8][16][32]= 4096
#define LC_OFF (LZ_OFF + 4096)          // 128
#define LSMEM_FLOATS (LC_OFF + 128)     // 28800
#define LSMEM_BYTES (LSMEM_FLOATS * 4)  // 115200 B

// ---- scratch (device globals: allocation-free) ----
__device__ float g_x[MM * EE];        // gathered embeddings  [4096, 300]
__device__ float g_xz[MM * G4];       // x @ W_x + b          [4096, 2048]
__device__ float g_hp[2][HH * BB];    // h ping-pong, [u][b] layout (k-major!)
__device__ __nv_bfloat16 g_A[(long long)MM * GKK];   // [4096,1536]  = [Ah|Al|Ah]
__device__ __nv_bfloat16 g_B[(long long)VV * GKK];   // [32000,1536] = [Bh|Bh|Bl]
__device__ unsigned g_bar_cnt = 0;
__device__ unsigned g_bar_gen = 0;

// ===========================================================================
__device__ __forceinline__ uint32_t smem_u32(const void* p) {
    uint32_t a;
    asm("{ .reg .u64 t; cvta.to.shared.u64 t, %1; cvt.u32.u64 %0, t; }" : "=r"(a) : "l"(p));
    return a;
}
__device__ __forceinline__ void cp_async16(uint32_t s, const void* g) {
    asm volatile("cp.async.cg.shared.global [%0], [%1], 16;" :: "r"(s), "l"(g));
}

// ---------------------------------------------------------------------------
// embedding gather
// ---------------------------------------------------------------------------
__global__ void gather_kernel(const int* __restrict__ inputs,
                              const float* __restrict__ emb) {
    int i = blockIdx.x * blockDim.x + threadIdx.x;
    if (i < MM * EE) {
        int m = i / EE;
        int e = i - m * EE;
        g_x[i] = emb[(long long)inputs[m] * EE + e];
    }
}

// ---------------------------------------------------------------------------
// init: transpose hidden [B,H] -> g_hp[0] [H,B]
// ---------------------------------------------------------------------------
__global__ void init_h_kernel(const float* __restrict__ hidden) {
    int i = blockIdx.x * blockDim.x + threadIdx.x;
    if (i < BB * HH) {
        int b = i / HH;
        int u = i - b * HH;
        g_hp[0][u * BB + b] = hidden[i];
    }
}

// ---------------------------------------------------------------------------
// fp32 SGEMM + bias (xz = x @ W_x + b only)
// ---------------------------------------------------------------------------
template<int BM, int BN, int BK, int TM, int TN>
__global__ void __launch_bounds__(256, 2)
sgemm_bias_kernel(const float* __restrict__ A, const float* __restrict__ Bm,
                  const float* __restrict__ bias, float* __restrict__ C,
                  int M, int N, int K) {
    __shared__ float As[BK][BM];
    __shared__ float Bs[BK][BN];
    const int tid  = threadIdx.x;
    const int brow = blockIdx.y * BM;
    const int bcol = blockIdx.x * BN;
    const int tx = tid % (BN / TN);
    const int ty = tid / (BN / TN);

    float acc[TM][TN];
#pragma unroll
    for (int i = 0; i < TM; i++)
#pragma unroll
        for (int j = 0; j < TN; j++) acc[i][j] = 0.f;

    for (int k0 = 0; k0 < K; k0 += BK) {
#pragma unroll
        for (int i = 0; i < BM * BK / 256; i++) {
            int idx = tid + i * 256;
            int r = idx / BK, c = idx % BK;
            As[c][r] = (k0 + c < K) ? A[(long long)(brow + r) * K + k0 + c] : 0.f;
        }
#pragma unroll
        for (int i = 0; i < BK * BN / 256; i++) {
            int idx = tid + i * 256;
            int r = idx / BN, c = idx % BN;
            Bs[r][c] = (k0 + r < K) ? Bm[(long long)(k0 + r) * N + bcol + c] : 0.f;
        }
        __syncthreads();
#pragma unroll
        for (int k = 0; k < BK; k++) {
            float ra[TM], rb[TN];
#pragma unroll
            for (int i = 0; i < TM; i++) ra[i] = As[k][ty * TM + i];
#pragma unroll
            for (int j = 0; j < TN; j++) rb[j] = Bs[k][tx * TN + j];
#pragma unroll
            for (int i = 0; i < TM; i++)
#pragma unroll
                for (int j = 0; j < TN; j++) acc[i][j] += ra[i] * rb[j];
        }
        __syncthreads();
    }
#pragma unroll
    for (int i = 0; i < TM; i++) {
        long long row = brow + ty * TM + i;
#pragma unroll
        for (int j = 0; j < TN; j++) {
            int col = bcol + tx * TN + j;
            C[row * N + col] = acc[i][j] + bias[col];
        }
    }
}

// ---------------------------------------------------------------------------
// Persistent LSTM, register-tiled.
// CTA c owns units [4c,4c+4) -> 16 gate-cols (c = uu*4+g). Wh slice in smem
// as sw[k][16]; h as sh[k][32] ([u][b] global layout, loaded per warp).
// Thread (tb,tc,kg): 4b x 4c register tile over k-range [kg*64, kg*64+64).
// ---------------------------------------------------------------------------
__global__ void __launch_bounds__(256, 1)
lstm_persistent(const float* __restrict__ Wh, const float* __restrict__ cell,
                float* __restrict__ out) {
    extern __shared__ float sm[];
    float* sw = sm + LW_OFF;           // [512][16]
    float* sh = sm + LH_OFF;           // [512][32]
    float* sz = sm + LZ_OFF;           // [8][16][32]
    float* sc = sm + LC_OFF;           // [128]
    const uint32_t sbase = smem_u32(sm);
    const int tid = threadIdx.x;
    const int lane = tid & 31;
    const int tb = tid & 7;            // b-group (4 batches)
    const int tc = (tid >> 3) & 3;     // c-group (4 cols)
    const int kg = tid >> 5;           // k-group (64 k) == warp id
    const int u0 = blockIdx.x * 4;

    __shared__ unsigned s_gen0;
    if (tid == 0) s_gen0 = *(volatile unsigned*)&g_bar_gen;

    // one-time: Wh slice -> sw[k][c], c = uu*4 + g
#pragma unroll
    for (int it = 0; it < 32; it++) {
        int e = tid + it * 256;        // 0..8191
        int k = e >> 4, c = e & 15;
        int uu = c >> 2, g = c & 3;
        sw[e] = Wh[(long long)k * G4 + g * HH + u0 + uu];
    }
    if (tid < 128) sc[tid] = cell[(tid & 31) * HH + u0 + (tid >> 5)];
    __syncthreads();
    const unsigned gen0 = s_gen0;

    for (int t = 0; t < TT; t++) {
        const float* __restrict__ hsrc = g_hp[t & 1];        // [u][b]
        float* __restrict__ hdst       = g_hp[(t + 1) & 1];

        // warp kg loads its own k-range: 64 rows x 32 floats = 8KB
        {
            const float* src = hsrc + kg * 64 * BB;
            uint32_t dst = sbase + (LH_OFF + kg * 64 * BB) * 4;
#pragma unroll
            for (int j = 0; j < 16; j++) {
                int e = lane + j * 32;       // 0..511 16B-chunks
                cp_async16(dst + e * 16, src + e * 4);
            }
            asm volatile("cp.async.commit_group;" ::: "memory");
            asm volatile("cp.async.wait_group 0;" ::: "memory");
            __syncwarp();
        }

        // 4b x 4c register tile over 64 k
        float a00=0,a01=0,a02=0,a03=0, a10=0,a11=0,a12=0,a13=0;
        float a20=0,a21=0,a22=0,a23=0, a30=0,a31=0,a32=0,a33=0;
        const float* hb = sh + kg * 64 * 32 + tb * 4;
        const float* wb = sw + kg * 64 * 16 + tc * 4;
#pragma unroll 8
        for (int k = 0; k < 64; k++) {
            float4 h4 = *(const float4*)(hb + k * 32);
            float4 w4 = *(const float4*)(wb + k * 16);
            a00 += h4.x * w4.x; a01 += h4.x * w4.y; a02 += h4.x * w4.z; a03 += h4.x * w4.w;
            a10 += h4.y * w4.x; a11 += h4.y * w4.y; a12 += h4.y * w4.z; a13 += h4.y * w4.w;
            a20 += h4.z * w4.x; a21 += h4.z * w4.y; a22 += h4.z * w4.z; a23 += h4.z * w4.w;
            a30 += h4.w * w4.x; a31 += h4.w * w4.y; a32 += h4.w * w4.z; a33 += h4.w * w4.w;
        }
        // partials -> sz[kg][c][b]
        {
            float* zb = sz + kg * 512 + tb * 4;
            *(float4*)(zb + (tc * 4 + 0) * 32) = make_float4(a00, a10, a20, a30);
            *(float4*)(zb + (tc * 4 + 1) * 32) = make_float4(a01, a11, a21, a31);
            *(float4*)(zb + (tc * 4 + 2) * 32) = make_float4(a02, a12, a22, a32);
            *(float4*)(zb + (tc * 4 + 3) * 32) = make_float4(a03, a13, a23, a33);
        }
        __syncthreads();

        // reduce partials + nonlinearity (128 threads: 32 b x 4 units)
        if (tid < 128) {
            int bb = tid & 31, uu = tid >> 5;
            float z[4];
#pragma unroll
            for (int g = 0; g < 4; g++) {
                int c = uu * 4 + g;
                float s = 0.f;
#pragma unroll
                for (int q = 0; q < 8; q++) s += sz[q * 512 + c * 32 + bb];
                z[g] = s;
            }
            const float* xzr = g_xz + (long long)(bb * TT + t) * G4 + u0 + uu;
            float zi = z[0] + xzr[0 * HH];
            float zf = z[1] + xzr[1 * HH];
            float zg = z[2] + xzr[2 * HH];
            float zo = z[3] + xzr[3 * HH];
            float si = 1.f / (1.f + expf(-zi));
            float sf = 1.f / (1.f + expf(-zf));
            float so = 1.f / (1.f + expf(-zo));
            float cn = sf * sc[tid] + si * tanhf(zg);
            float hn = so * tanhf(cn);
            sc[tid] = cn;
            hdst[(u0 + uu) * BB + bb] = hn;          // [u][b] for next step
            // bf16 split write straight into A' = [Ah | Al | Ah]
            __nv_bfloat16 hi = __float2bfloat16(hn);
            __nv_bfloat16 lo = __float2bfloat16(hn - __bfloat162float(hi));
            long long abase = (long long)(bb * TT + t) * GKK + u0 + uu;
            g_A[abase]        = hi;
            g_A[abase + 512]  = lo;
            g_A[abase + 1024] = hi;
            if (t == TT - 1)
                out[LOGITS_ELEMS + bb * HH + u0 + uu] = hn;
        }

        // grid barrier
        __syncthreads();
        if (tid == 0) {
            __threadfence();
            if (atomicAdd(&g_bar_cnt, 1u) == NCTA - 1) {
                *(volatile unsigned*)&g_bar_cnt = 0;
                __threadfence();
                atomicAdd(&g_bar_gen, 1u);
            } else {
                while (*(volatile unsigned*)&g_bar_gen - gen0 < (unsigned)(t + 1)) { }
            }
            __threadfence();
        }
        __syncthreads();
    }

    if (tid < 128) {
        out[LOGITS_ELEMS + BB * HH + (tid & 31) * HH + u0 + (tid >> 5)] = sc[tid];
    }
}

// ---------------------------------------------------------------------------
// Split + transpose W_out [512,32000] -> B' [32000,1536] = [Bh | Bh | Bl]
// ---------------------------------------------------------------------------
__global__ void split_wout_kernel(const float* __restrict__ W) {
    __shared__ float t[32][33];
    int n0 = blockIdx.x * 32, k0 = blockIdx.y * 32;
    int tx = threadIdx.x, ty = threadIdx.y;   // 32 x 8
#pragma unroll
    for (int i = 0; i < 4; i++) {
        int k = ty + i * 8;
        t[k][tx] = W[(long long)(k0 + k) * VV + n0 + tx];
    }
    __syncthreads();
#pragma unroll
    for (int i = 0; i < 4; i++) {
        int n = ty + i * 8;
        float v = t[tx][n];
        __nv_bfloat16 hi = __float2bfloat16(v);
        __nv_bfloat16 lo = __float2bfloat16(v - __bfloat162float(hi));
        long long base = (long long)(n0 + n) * GKK + k0;
        g_B[base + tx]        = hi;
        g_B[base + 512 + tx]  = hi;
        g_B[base + 1024 + tx] = lo;
    }
}

// ---------------------------------------------------------------------------
// HMMA bf16 GEMM: C[4096,32000] = A'[4096,1536] @ B'[32000,1536]^T + bout
// ---------------------------------------------------------------------------
__global__ void __launch_bounds__(OTHREADS, 1)
out_gemm_hmma(const __nv_bfloat16* __restrict__ A, const __nv_bfloat16* __restrict__ B,
              const float* __restrict__ bout, float* __restrict__ C) {
    extern __shared__ char smem[];
    const int tid  = threadIdx.x;
    const int lane = tid & 31;
    const int wid  = tid >> 5;
    const int wm   = wid & 3;
    const int wn   = wid >> 2;
    const int m0 = blockIdx.x * OBM;
    const int n0 = blockIdx.y * OBN;
    const uint32_t sbase = smem_u32(smem);

    auto load_stage = [&](int s, int kt) {
        uint32_t sA = sbase + s * STAGE_BYTES;
        uint32_t sB = sA + A_ST_BYTES;
        long long k0 = (long long)kt * OBK;
        {
            int r = tid >> 2, ch = tid & 3;
            cp_async16(sA + r * 80 + ch * 16,
                       A + (long long)(m0 + r) * GKK + k0 + ch * 8);
        }
#pragma unroll
        for (int i = 0; i < 2; i++) {
            int idx = tid + i * 512;
            int r = idx >> 2, ch = idx & 3;
            cp_async16(sB + r * 80 + ch * 16,
                       B + (long long)(n0 + r) * GKK + k0 + ch * 8);
        }
        asm volatile("cp.async.commit_group;" ::: "memory");
    };

    float acc[2][8][4];
#pragma unroll
    for (int i = 0; i < 2; i++)
#pragma unroll
        for (int j = 0; j < 8; j++)
#pragma unroll
            for (int q = 0; q < 4; q++) acc[i][j][q] = 0.f;

    const int KT = GKK / OBK;   // 48
#pragma unroll
    for (int s = 0; s < OSTAGES - 1; s++) load_stage(s, s);

    for (int kt = 0; kt < KT; kt++) {
        asm volatile("cp.async.wait_group %0;" :: "n"(OSTAGES - 2));
        __syncthreads();
        if (kt + OSTAGES - 1 < KT)
            load_stage((kt + OSTAGES - 1) % OSTAGES, kt + OSTAGES - 1);

        uint32_t sA = sbase + (kt % OSTAGES) * STAGE_BYTES;
        uint32_t sB = sA + A_ST_BYTES;
        const int krow = lane & 15;
#pragma unroll
        for (int ks = 0; ks < 2; ks++) {
            const int kcolb = (ks * 16 + (lane >> 4) * 8) * 2;
            uint32_t a[2][4], bb[4][4];
#pragma unroll
            for (int mt = 0; mt < 2; mt++) {
                uint32_t addr = sA + (wm * 32 + mt * 16 + krow) * 80 + kcolb;
                asm volatile("ldmatrix.sync.aligned.m8n8.x4.shared.b16 {%0,%1,%2,%3}, [%4];"
                    : "=r"(a[mt][0]), "=r"(a[mt][1]), "=r"(a[mt][2]), "=r"(a[mt][3])
                    : "r"(addr));
            }
#pragma unroll
            for (int np = 0; np < 4; np++) {
                uint32_t addr = sB + (wn * 64 + np * 16 + krow) * 80 + kcolb;
                asm volatile("ldmatrix.sync.aligned.m8n8.x4.shared.b16 {%0,%1,%2,%3}, [%4];"
                    : "=r"(bb[np][0]), "=r"(bb[np][1]), "=r"(bb[np][2]), "=r"(bb[np][3])
                    : "r"(addr));
            }
#pragma unroll
            for (int mt = 0; mt < 2; mt++)
#pragma unroll
                for (int nt = 0; nt < 8; nt++) {
                    uint32_t b0 = bb[nt >> 1][nt & 1];
                    uint32_t b1 = bb[nt >> 1][(nt & 1) + 2];
                    asm volatile(
                        "mma.sync.aligned.m16n8k16.row.col.f32.bf16.bf16.f32 "
                        "{%0,%1,%2,%3}, {%4,%5,%6,%7}, {%8,%9}, {%0,%1,%2,%3};"
                        : "+f"(acc[mt][nt][0]), "+f"(acc[mt][nt][1]),
                          "+f"(acc[mt][nt][2]), "+f"(acc[mt][nt][3])
                        : "r"(a[mt][0]), "r"(a[mt][1]), "r"(a[mt][2]), "r"(a[mt][3]),
                          "r"(b0), "r"(b1));
                }
        }
    }

    const int row_b = m0 + wm * 32 + (lane >> 2);
    const int col_b = n0 + wn * 64 + (lane & 3) * 2;
#pragma unroll
    for (int nt = 0; nt < 8; nt++) {
        int col = col_b + nt * 8;
        float b0v = __ldg(bout + col);
        float b1v = __ldg(bout + col + 1);
#pragma unroll
        for (int mt = 0; mt < 2; mt++) {
            long long r0 = row_b + mt * 16;
            float2 v0 = make_float2(acc[mt][nt][0] + b0v, acc[mt][nt][1] + b1v);
            float2 v1 = make_float2(acc[mt][nt][2] + b0v, acc[mt][nt][3] + b1v);
            *(float2*)&C[r0 * VV + col]       = v0;
            *(float2*)&C[(r0 + 8) * VV + col] = v1;
        }
    }
}

// ---------------------------------------------------------------------------
extern "C" void kernel_launch(void* const* d_in, const int* in_sizes, int n_in,
                              void* d_out, int out_size) {
    const int*   inputs = (const int*)  d_in[0];
    const float* hidden = (const float*)d_in[1];
    const float* cell   = (const float*)d_in[2];
    const float* emb    = (const float*)d_in[3];
    const float* Wx     = (const float*)d_in[4];
    const float* Wh     = (const float*)d_in[5];
    const float* bias   = (const float*)d_in[6];
    const float* Wout   = (const float*)d_in[7];
    const float* bout   = (const float*)d_in[8];
    float* out = (float*)d_out;

    float *px, *pxz;
    __nv_bfloat16 *pA, *pB;
    cudaGetSymbolAddress((void**)&px,  g_x);
    cudaGetSymbolAddress((void**)&pxz, g_xz);
    cudaGetSymbolAddress((void**)&pA,  g_A);
    cudaGetSymbolAddress((void**)&pB,  g_B);

    cudaFuncSetAttribute(out_gemm_hmma,
                         cudaFuncAttributeMaxDynamicSharedMemorySize, OSMEM);
    cudaFuncSetAttribute(lstm_persistent,
                         cudaFuncAttributeMaxDynamicSharedMemorySize, LSMEM_BYTES);

    // 1. embedding gather
    gather_kernel<<<(MM * EE + 255) / 256, 256>>>(inputs, emb);

    // 2. init h (transposed)
    init_h_kernel<<<(BB * HH + 255) / 256, 256>>>(hidden);

    // 3. xz = x @ W_x + b   (4096 x 2048 x 300)  fp32
    {
        dim3 grid(G4 / 128, MM / 128);
        sgemm_bias_kernel<128,128,8,8,8><<<grid, 256>>>(px, Wx, bias, pxz,
                                                        MM, G4, EE);
    }

    // 4. split W_out (independent of LSTM)
    {
        dim3 grid(VV / 32, HH / 32);
        split_wout_kernel<<<grid, dim3(32, 8)>>>(Wout);
    }

    // 5. all 128 LSTM steps in ONE persistent launch
    lstm_persistent<<<NCTA, 256, LSMEM_BYTES>>>(Wh, cell, out);

    // 6. logits = A' @ B'^T + b_out  (HMMA bf16 split GEMM)
    {
        dim3 grid(MM / OBM, VV / OBN);
        out_gemm_hmma<<<grid, OTHREADS, OSMEM>>>(pA, pB, bout, out);
    }
}

// round 7
// speedup vs baseline: 2.0529x; 1.0422x over previous
#include <cuda_runtime.h>
#include <cuda_bf16.h>
#include <math.h>
#include <cstdint>

#define BB 32
#define TT 128
#define VV 32000
#define EE 300
#define HH 512
#define G4 (4*HH)      // 2048
#define MM (BB*TT)     // 4096
#define LOGITS_ELEMS ((long long)MM * VV)   // 131072000

// split-bf16 GEMM dims
#define GKK 1536       // 3 * 512 stacked K

// HMMA output-GEMM tiling (128x128, 256 thr, 4 stages, 2 CTA/SM)
#define OBM 128
#define OBN 128
#define OBK 32
#define OSTAGES 4
#define OTHREADS 256
#define A_ST_BYTES (128*80)
#define B_ST_BYTES (128*80)
#define STAGE_BYTES (A_ST_BYTES + B_ST_BYTES)   // 20480
#define OSMEM (OSTAGES*STAGE_BYTES)             // 81920

// persistent LSTM (register-tiled)
#define NCTA 128
#define LW_OFF 0                        // [512][16]  = 8192
#define LH_OFF 8192                     // [512][32]  = 16384
#define LZ_OFF (LH_OFF + 16384)         // [8][16][32]= 4096
#define LC_OFF (LZ_OFF + 4096)          // 128
#define LSMEM_FLOATS (LC_OFF + 128)     // 28800
#define LSMEM_BYTES (LSMEM_FLOATS * 4)  // 115200 B

// ---- scratch (device globals: allocation-free) ----
__device__ float g_x[MM * EE];        // gathered embeddings  [4096, 300]
__device__ float g_xz[MM * G4];       // x @ W_x + b          [4096, 2048]
__device__ float g_hp[2][HH * BB];    // h ping-pong, [u][b] layout (k-major)
__device__ __nv_bfloat16 g_A[(long long)MM * GKK];   // [4096,1536]  = [Ah|Al|Ah]
__device__ __nv_bfloat16 g_B[(long long)VV * GKK];   // [32000,1536] = [Bh|Bh|Bl]
__device__ unsigned g_bar_cnt = 0;
__device__ unsigned g_bar_gen = 0;

// ===========================================================================
__device__ __forceinline__ uint32_t smem_u32(const void* p) {
    uint32_t a;
    asm("{ .reg .u64 t; cvta.to.shared.u64 t, %1; cvt.u32.u64 %0, t; }" : "=r"(a) : "l"(p));
    return a;
}
__device__ __forceinline__ void cp_async16(uint32_t s, const void* g) {
    asm volatile("cp.async.cg.shared.global [%0], [%1], 16;" :: "r"(s), "l"(g));
}

// ---------------------------------------------------------------------------
// embedding gather
// ---------------------------------------------------------------------------
__global__ void gather_kernel(const int* __restrict__ inputs,
                              const float* __restrict__ emb) {
    int i = blockIdx.x * blockDim.x + threadIdx.x;
    if (i < MM * EE) {
        int m = i / EE;
        int e = i - m * EE;
        g_x[i] = emb[(long long)inputs[m] * EE + e];
    }
}

// ---------------------------------------------------------------------------
// init: transpose hidden [B,H] -> g_hp[0] [H,B]
// ---------------------------------------------------------------------------
__global__ void init_h_kernel(const float* __restrict__ hidden) {
    int i = blockIdx.x * blockDim.x + threadIdx.x;
    if (i < BB * HH) {
        int b = i / HH;
        int u = i - b * HH;
        g_hp[0][u * BB + b] = hidden[i];
    }
}

// ---------------------------------------------------------------------------
// fp32 SGEMM + bias (xz = x @ W_x + b only)
// ---------------------------------------------------------------------------
template<int BM, int BN, int BK, int TM, int TN>
__global__ void __launch_bounds__(256, 2)
sgemm_bias_kernel(const float* __restrict__ A, const float* __restrict__ Bm,
                  const float* __restrict__ bias, float* __restrict__ C,
                  int M, int N, int K) {
    __shared__ float As[BK][BM];
    __shared__ float Bs[BK][BN];
    const int tid  = threadIdx.x;
    const int brow = blockIdx.y * BM;
    const int bcol = blockIdx.x * BN;
    const int tx = tid % (BN / TN);
    const int ty = tid / (BN / TN);

    float acc[TM][TN];
#pragma unroll
    for (int i = 0; i < TM; i++)
#pragma unroll
        for (int j = 0; j < TN; j++) acc[i][j] = 0.f;

    for (int k0 = 0; k0 < K; k0 += BK) {
#pragma unroll
        for (int i = 0; i < BM * BK / 256; i++) {
            int idx = tid + i * 256;
            int r = idx / BK, c = idx % BK;
            As[c][r] = (k0 + c < K) ? A[(long long)(brow + r) * K + k0 + c] : 0.f;
        }
#pragma unroll
        for (int i = 0; i < BK * BN / 256; i++) {
            int idx = tid + i * 256;
            int r = idx / BN, c = idx % BN;
            Bs[r][c] = (k0 + r < K) ? Bm[(long long)(k0 + r) * N + bcol + c] : 0.f;
        }
        __syncthreads();
#pragma unroll
        for (int k = 0; k < BK; k++) {
            float ra[TM], rb[TN];
#pragma unroll
            for (int i = 0; i < TM; i++) ra[i] = As[k][ty * TM + i];
#pragma unroll
            for (int j = 0; j < TN; j++) rb[j] = Bs[k][tx * TN + j];
#pragma unroll
            for (int i = 0; i < TM; i++)
#pragma unroll
                for (int j = 0; j < TN; j++) acc[i][j] += ra[i] * rb[j];
        }
        __syncthreads();
    }
#pragma unroll
    for (int i = 0; i < TM; i++) {
        long long row = brow + ty * TM + i;
#pragma unroll
        for (int j = 0; j < TN; j++) {
            int col = bcol + tx * TN + j;
            C[row * N + col] = acc[i][j] + bias[col];
        }
    }
}

// ---------------------------------------------------------------------------
// Persistent LSTM, register-tiled (unchanged)
// ---------------------------------------------------------------------------
__global__ void __launch_bounds__(256, 1)
lstm_persistent(const float* __restrict__ Wh, const float* __restrict__ cell,
                float* __restrict__ out) {
    extern __shared__ float sm[];
    float* sw = sm + LW_OFF;           // [512][16]
    float* sh = sm + LH_OFF;           // [512][32]
    float* sz = sm + LZ_OFF;           // [8][16][32]
    float* sc = sm + LC_OFF;           // [128]
    const uint32_t sbase = smem_u32(sm);
    const int tid = threadIdx.x;
    const int lane = tid & 31;
    const int tb = tid & 7;
    const int tc = (tid >> 3) & 3;
    const int kg = tid >> 5;
    const int u0 = blockIdx.x * 4;

    __shared__ unsigned s_gen0;
    if (tid == 0) s_gen0 = *(volatile unsigned*)&g_bar_gen;

#pragma unroll
    for (int it = 0; it < 32; it++) {
        int e = tid + it * 256;
        int k = e >> 4, c = e & 15;
        int uu = c >> 2, g = c & 3;
        sw[e] = Wh[(long long)k * G4 + g * HH + u0 + uu];
    }
    if (tid < 128) sc[tid] = cell[(tid & 31) * HH + u0 + (tid >> 5)];
    __syncthreads();
    const unsigned gen0 = s_gen0;

    for (int t = 0; t < TT; t++) {
        const float* __restrict__ hsrc = g_hp[t & 1];
        float* __restrict__ hdst       = g_hp[(t + 1) & 1];

        {
            const float* src = hsrc + kg * 64 * BB;
            uint32_t dst = sbase + (LH_OFF + kg * 64 * BB) * 4;
#pragma unroll
            for (int j = 0; j < 16; j++) {
                int e = lane + j * 32;
                cp_async16(dst + e * 16, src + e * 4);
            }
            asm volatile("cp.async.commit_group;" ::: "memory");
            asm volatile("cp.async.wait_group 0;" ::: "memory");
            __syncwarp();
        }

        float a00=0,a01=0,a02=0,a03=0, a10=0,a11=0,a12=0,a13=0;
        float a20=0,a21=0,a22=0,a23=0, a30=0,a31=0,a32=0,a33=0;
        const float* hb = sh + kg * 64 * 32 + tb * 4;
        const float* wb = sw + kg * 64 * 16 + tc * 4;
#pragma unroll 8
        for (int k = 0; k < 64; k++) {
            float4 h4 = *(const float4*)(hb + k * 32);
            float4 w4 = *(const float4*)(wb + k * 16);
            a00 += h4.x * w4.x; a01 += h4.x * w4.y; a02 += h4.x * w4.z; a03 += h4.x * w4.w;
            a10 += h4.y * w4.x; a11 += h4.y * w4.y; a12 += h4.y * w4.z; a13 += h4.y * w4.w;
            a20 += h4.z * w4.x; a21 += h4.z * w4.y; a22 += h4.z * w4.z; a23 += h4.z * w4.w;
            a30 += h4.w * w4.x; a31 += h4.w * w4.y; a32 += h4.w * w4.z; a33 += h4.w * w4.w;
        }
        {
            float* zb = sz + kg * 512 + tb * 4;
            *(float4*)(zb + (tc * 4 + 0) * 32) = make_float4(a00, a10, a20, a30);
            *(float4*)(zb + (tc * 4 + 1) * 32) = make_float4(a01, a11, a21, a31);
            *(float4*)(zb + (tc * 4 + 2) * 32) = make_float4(a02, a12, a22, a32);
            *(float4*)(zb + (tc * 4 + 3) * 32) = make_float4(a03, a13, a23, a33);
        }
        __syncthreads();

        if (tid < 128) {
            int bb = tid & 31, uu = tid >> 5;
            float z[4];
#pragma unroll
            for (int g = 0; g < 4; g++) {
                int c = uu * 4 + g;
                float s = 0.f;
#pragma unroll
                for (int q = 0; q < 8; q++) s += sz[q * 512 + c * 32 + bb];
                z[g] = s;
            }
            const float* xzr = g_xz + (long long)(bb * TT + t) * G4 + u0 + uu;
            float zi = z[0] + xzr[0 * HH];
            float zf = z[1] + xzr[1 * HH];
            float zg = z[2] + xzr[2 * HH];
            float zo = z[3] + xzr[3 * HH];
            float si = 1.f / (1.f + expf(-zi));
            float sf = 1.f / (1.f + expf(-zf));
            float so = 1.f / (1.f + expf(-zo));
            float cn = sf * sc[tid] + si * tanhf(zg);
            float hn = so * tanhf(cn);
            sc[tid] = cn;
            hdst[(u0 + uu) * BB + bb] = hn;
            __nv_bfloat16 hi = __float2bfloat16(hn);
            __nv_bfloat16 lo = __float2bfloat16(hn - __bfloat162float(hi));
            long long abase = (long long)(bb * TT + t) * GKK + u0 + uu;
            g_A[abase]        = hi;
            g_A[abase + 512]  = lo;
            g_A[abase + 1024] = hi;
            if (t == TT - 1)
                out[LOGITS_ELEMS + bb * HH + u0 + uu] = hn;
        }

        __syncthreads();
        if (tid == 0) {
            __threadfence();
            if (atomicAdd(&g_bar_cnt, 1u) == NCTA - 1) {
                *(volatile unsigned*)&g_bar_cnt = 0;
                __threadfence();
                atomicAdd(&g_bar_gen, 1u);
            } else {
                while (*(volatile unsigned*)&g_bar_gen - gen0 < (unsigned)(t + 1)) { }
            }
            __threadfence();
        }
        __syncthreads();
    }

    if (tid < 128) {
        out[LOGITS_ELEMS + BB * HH + (tid & 31) * HH + u0 + (tid >> 5)] = sc[tid];
    }
}

// ---------------------------------------------------------------------------
// Split + transpose W_out [512,32000] -> B' [32000,1536] = [Bh | Bh | Bl]
// ---------------------------------------------------------------------------
__global__ void split_wout_kernel(const float* __restrict__ W) {
    __shared__ float t[32][33];
    int n0 = blockIdx.x * 32, k0 = blockIdx.y * 32;
    int tx = threadIdx.x, ty = threadIdx.y;   // 32 x 8
#pragma unroll
    for (int i = 0; i < 4; i++) {
        int k = ty + i * 8;
        t[k][tx] = W[(long long)(k0 + k) * VV + n0 + tx];
    }
    __syncthreads();
#pragma unroll
    for (int i = 0; i < 4; i++) {
        int n = ty + i * 8;
        float v = t[tx][n];
        __nv_bfloat16 hi = __float2bfloat16(v);
        __nv_bfloat16 lo = __float2bfloat16(v - __bfloat162float(hi));
        long long base = (long long)(n0 + n) * GKK + k0;
        g_B[base + tx]        = hi;
        g_B[base + 512 + tx]  = hi;
        g_B[base + 1024 + tx] = lo;
    }
}

// ---------------------------------------------------------------------------
// HMMA bf16 GEMM: C[4096,32000] = A'[4096,1536] @ B'[32000,1536]^T + bout
// CTA 128x128, 256 thr (4m x 2n warps, warp tile 32x64), 4-stage, 2 CTA/SM.
// ---------------------------------------------------------------------------
__global__ void __launch_bounds__(OTHREADS, 2)
out_gemm_hmma(const __nv_bfloat16* __restrict__ A, const __nv_bfloat16* __restrict__ B,
              const float* __restrict__ bout, float* __restrict__ C) {
    extern __shared__ char smem[];
    const int tid  = threadIdx.x;
    const int lane = tid & 31;
    const int wid  = tid >> 5;         // 0..7
    const int wm   = wid & 3;          // m offset wm*32
    const int wn   = wid >> 2;         // n offset wn*64
    const int m0 = blockIdx.x * OBM;
    const int n0 = blockIdx.y * OBN;
    const uint32_t sbase = smem_u32(smem);

    auto load_stage = [&](int s, int kt) {
        uint32_t sA = sbase + s * STAGE_BYTES;
        uint32_t sB = sA + A_ST_BYTES;
        long long k0 = (long long)kt * OBK;
        // A: 128 rows x 4 chunks of 16B = 512 chunks (2 iters of 256 thr)
#pragma unroll
        for (int i = 0; i < 2; i++) {
            int idx = tid + i * 256;
            int r = idx >> 2, ch = idx & 3;
            cp_async16(sA + r * 80 + ch * 16,
                       A + (long long)(m0 + r) * GKK + k0 + ch * 8);
        }
        // B: same shape
#pragma unroll
        for (int i = 0; i < 2; i++) {
            int idx = tid + i * 256;
            int r = idx >> 2, ch = idx & 3;
            cp_async16(sB + r * 80 + ch * 16,
                       B + (long long)(n0 + r) * GKK + k0 + ch * 8);
        }
        asm volatile("cp.async.commit_group;" ::: "memory");
    };

    float acc[2][8][4];
#pragma unroll
    for (int i = 0; i < 2; i++)
#pragma unroll
        for (int j = 0; j < 8; j++)
#pragma unroll
            for (int q = 0; q < 4; q++) acc[i][j][q] = 0.f;

    const int KT = GKK / OBK;   // 48
#pragma unroll
    for (int s = 0; s < OSTAGES - 1; s++) load_stage(s, s);

    for (int kt = 0; kt < KT; kt++) {
        asm volatile("cp.async.wait_group %0;" :: "n"(OSTAGES - 2));
        __syncthreads();
        if (kt + OSTAGES - 1 < KT)
            load_stage((kt + OSTAGES - 1) % OSTAGES, kt + OSTAGES - 1);

        uint32_t sA = sbase + (kt % OSTAGES) * STAGE_BYTES;
        uint32_t sB = sA + A_ST_BYTES;
        const int krow = lane & 15;
#pragma unroll
        for (int ks = 0; ks < 2; ks++) {
            const int kcolb = (ks * 16 + (lane >> 4) * 8) * 2;
            uint32_t a[2][4], bb[4][4];
#pragma unroll
            for (int mt = 0; mt < 2; mt++) {
                uint32_t addr = sA + (wm * 32 + mt * 16 + krow) * 80 + kcolb;
                asm volatile("ldmatrix.sync.aligned.m8n8.x4.shared.b16 {%0,%1,%2,%3}, [%4];"
                    : "=r"(a[mt][0]), "=r"(a[mt][1]), "=r"(a[mt][2]), "=r"(a[mt][3])
                    : "r"(addr));
            }
#pragma unroll
            for (int np = 0; np < 4; np++) {
                uint32_t addr = sB + (wn * 64 + np * 16 + krow) * 80 + kcolb;
                asm volatile("ldmatrix.sync.aligned.m8n8.x4.shared.b16 {%0,%1,%2,%3}, [%4];"
                    : "=r"(bb[np][0]), "=r"(bb[np][1]), "=r"(bb[np][2]), "=r"(bb[np][3])
                    : "r"(addr));
            }
#pragma unroll
            for (int mt = 0; mt < 2; mt++)
#pragma unroll
                for (int nt = 0; nt < 8; nt++) {
                    uint32_t b0 = bb[nt >> 1][nt & 1];
                    uint32_t b1 = bb[nt >> 1][(nt & 1) + 2];
                    asm volatile(
                        "mma.sync.aligned.m16n8k16.row.col.f32.bf16.bf16.f32 "
                        "{%0,%1,%2,%3}, {%4,%5,%6,%7}, {%8,%9}, {%0,%1,%2,%3};"
                        : "+f"(acc[mt][nt][0]), "+f"(acc[mt][nt][1]),
                          "+f"(acc[mt][nt][2]), "+f"(acc[mt][nt][3])
                        : "r"(a[mt][0]), "r"(a[mt][1]), "r"(a[mt][2]), "r"(a[mt][3]),
                          "r"(b0), "r"(b1));
                }
        }
    }

    const int row_b = m0 + wm * 32 + (lane >> 2);
    const int col_b = n0 + wn * 64 + (lane & 3) * 2;
#pragma unroll
    for (int nt = 0; nt < 8; nt++) {
        int col = col_b + nt * 8;
        float b0v = __ldg(bout + col);
        float b1v = __ldg(bout + col + 1);
#pragma unroll
        for (int mt = 0; mt < 2; mt++) {
            long long r0 = row_b + mt * 16;
            float2 v0 = make_float2(acc[mt][nt][0] + b0v, acc[mt][nt][1] + b1v);
            float2 v1 = make_float2(acc[mt][nt][2] + b0v, acc[mt][nt][3] + b1v);
            *(float2*)&C[r0 * VV + col]       = v0;
            *(float2*)&C[(r0 + 8) * VV + col] = v1;
        }
    }
}

// ---------------------------------------------------------------------------
extern "C" void kernel_launch(void* const* d_in, const int* in_sizes, int n_in,
                              void* d_out, int out_size) {
    const int*   inputs = (const int*)  d_in[0];
    const float* hidden = (const float*)d_in[1];
    const float* cell   = (const float*)d_in[2];
    const float* emb    = (const float*)d_in[3];
    const float* Wx     = (const float*)d_in[4];
    const float* Wh     = (const float*)d_in[5];
    const float* bias   = (const float*)d_in[6];
    const float* Wout   = (const float*)d_in[7];
    const float* bout   = (const float*)d_in[8];
    float* out = (float*)d_out;

    float *px, *pxz;
    __nv_bfloat16 *pA, *pB;
    cudaGetSymbolAddress((void**)&px,  g_x);
    cudaGetSymbolAddress((void**)&pxz, g_xz);
    cudaGetSymbolAddress((void**)&pA,  g_A);
    cudaGetSymbolAddress((void**)&pB,  g_B);

    cudaFuncSetAttribute(out_gemm_hmma,
                         cudaFuncAttributeMaxDynamicSharedMemorySize, OSMEM);
    cudaFuncSetAttribute(lstm_persistent,
                         cudaFuncAttributeMaxDynamicSharedMemorySize, LSMEM_BYTES);

    // 1. embedding gather
    gather_kernel<<<(MM * EE + 255) / 256, 256>>>(inputs, emb);

    // 2. init h (transposed)
    init_h_kernel<<<(BB * HH + 255) / 256, 256>>>(hidden);

    // 3. xz = x @ W_x + b   (4096 x 2048 x 300)  fp32
    {
        dim3 grid(G4 / 128, MM / 128);
        sgemm_bias_kernel<128,128,8,8,8><<<grid, 256>>>(px, Wx, bias, pxz,
                                                        MM, G4, EE);
    }

    // 4. split W_out (independent of LSTM)
    {
        dim3 grid(VV / 32, HH / 32);
        split_wout_kernel<<<grid, dim3(32, 8)>>>(Wout);
    }

    // 5. all 128 LSTM steps in ONE persistent launch
    lstm_persistent<<<NCTA, 256, LSMEM_BYTES>>>(Wh, cell, out);

    // 6. logits = A' @ B'^T + b_out  (HMMA bf16 split GEMM, 2 CTA/SM)
    {
        dim3 grid(MM / OBM, VV / OBN);   // (32, 250)
        out_gemm_hmma<<<grid, OTHREADS, OSMEM>>>(pA, pB, bout, out);
    }
}

// round 8
// speedup vs baseline: 2.1157x; 1.0306x over previous
#include <cuda_runtime.h>
#include <cuda_bf16.h>
#include <math.h>
#include <cstdint>

#define BB 32
#define TT 128
#define VV 32000
#define EE 300
#define HH 512
#define G4 (4*HH)      // 2048
#define MM (BB*TT)     // 4096
#define LOGITS_ELEMS ((long long)MM * VV)   // 131072000

// split-bf16 stacked-K dims
#define GKK 1536       // out GEMM: 3 * 512
#define XSEG 320       // xz GEMM: 300 padded to 320 per segment
#define XKK (3*XSEG)   // 960

// HMMA GEMM tiling (128x128, 256 thr, 4 stages, 2 CTA/SM)
#define OBM 128
#define OBN 128
#define OBK 32
#define OSTAGES 4
#define OTHREADS 256
#define A_ST_BYTES (128*80)
#define B_ST_BYTES (128*80)
#define STAGE_BYTES (A_ST_BYTES + B_ST_BYTES)   // 20480
#define OSMEM (OSTAGES*STAGE_BYTES)             // 81920

// persistent LSTM (register-tiled)
#define NCTA 128
#define LW_OFF 0                        // [512][16]  = 8192
#define LH_OFF 8192                     // [512][32]  = 16384
#define LZ_OFF (LH_OFF + 16384)         // [8][16][32]= 4096
#define LC_OFF (LZ_OFF + 4096)          // 128
#define LSMEM_FLOATS (LC_OFF + 128)     // 28800
#define LSMEM_BYTES (LSMEM_FLOATS * 4)  // 115200 B

// ---- scratch (device globals: allocation-free) ----
__device__ float g_xz[MM * G4];       // x @ W_x + b          [4096, 2048]
__device__ float g_hp[2][HH * BB];    // h ping-pong, [u][b] layout (k-major)
__device__ __nv_bfloat16 g_A[(long long)MM * GKK];    // [4096,1536]  = [Ah|Al|Ah]
__device__ __nv_bfloat16 g_B[(long long)VV * GKK];    // [32000,1536] = [Bh|Bh|Bl]
__device__ __nv_bfloat16 g_A2[(long long)MM * XKK];   // [4096,960]   = [xh|xl|xh]
__device__ __nv_bfloat16 g_B2[(long long)G4 * XKK];   // [2048,960]   = [Wh|Wh|Wl]
__device__ unsigned g_bar_cnt = 0;
__device__ unsigned g_bar_gen = 0;

// ===========================================================================
__device__ __forceinline__ uint32_t smem_u32(const void* p) {
    uint32_t a;
    asm("{ .reg .u64 t; cvta.to.shared.u64 t, %1; cvt.u32.u64 %0, t; }" : "=r"(a) : "l"(p));
    return a;
}
__device__ __forceinline__ void cp_async16(uint32_t s, const void* g) {
    asm volatile("cp.async.cg.shared.global [%0], [%1], 16;" :: "r"(s), "l"(g));
}

// ---------------------------------------------------------------------------
// gather + split: A2[m] = [xh(320) | xl(320) | xh(320)], x = emb[inputs[m]]
// ---------------------------------------------------------------------------
__global__ void split_x_kernel(const int* __restrict__ inputs,
                               const float* __restrict__ emb) {
    int i = blockIdx.x * blockDim.x + threadIdx.x;   // over 4096*320
    if (i < MM * XSEG) {
        int m = i / XSEG;
        int k = i - m * XSEG;
        float v = (k < EE) ? emb[(long long)inputs[m] * EE + k] : 0.f;
        __nv_bfloat16 hi = __float2bfloat16(v);
        __nv_bfloat16 lo = __float2bfloat16(v - __bfloat162float(hi));
        long long base = (long long)m * XKK;
        g_A2[base + k]            = hi;
        g_A2[base + XSEG + k]     = lo;
        g_A2[base + 2*XSEG + k]   = hi;
    }
}

// ---------------------------------------------------------------------------
// split + transpose W_x [300,2048] -> B2 [2048,960] = [Wh | Wh | Wl]
// ---------------------------------------------------------------------------
__global__ void split_wx_kernel(const float* __restrict__ W) {
    __shared__ float t[32][33];
    int n0 = blockIdx.x * 32, k0 = blockIdx.y * 32;   // k0 in [0,320)
    int tx = threadIdx.x, ty = threadIdx.y;           // 32 x 8
#pragma unroll
    for (int i = 0; i < 4; i++) {
        int k = k0 + ty + i * 8;
        t[ty + i * 8][tx] = (k < EE) ? W[(long long)k * G4 + n0 + tx] : 0.f;
    }
    __syncthreads();
#pragma unroll
    for (int i = 0; i < 4; i++) {
        int n = ty + i * 8;
        float v = t[tx][n];
        __nv_bfloat16 hi = __float2bfloat16(v);
        __nv_bfloat16 lo = __float2bfloat16(v - __bfloat162float(hi));
        long long base = (long long)(n0 + n) * XKK + k0;
        g_B2[base + tx]            = hi;
        g_B2[base + XSEG + tx]     = hi;
        g_B2[base + 2*XSEG + tx]   = lo;
    }
}

// ---------------------------------------------------------------------------
// Split + transpose W_out [512,32000] -> B [32000,1536] = [Bh | Bh | Bl]
// ---------------------------------------------------------------------------
__global__ void split_wout_kernel(const float* __restrict__ W) {
    __shared__ float t[32][33];
    int n0 = blockIdx.x * 32, k0 = blockIdx.y * 32;
    int tx = threadIdx.x, ty = threadIdx.y;   // 32 x 8
#pragma unroll
    for (int i = 0; i < 4; i++) {
        int k = ty + i * 8;
        t[k][tx] = W[(long long)(k0 + k) * VV + n0 + tx];
    }
    __syncthreads();
#pragma unroll
    for (int i = 0; i < 4; i++) {
        int n = ty + i * 8;
        float v = t[tx][n];
        __nv_bfloat16 hi = __float2bfloat16(v);
        __nv_bfloat16 lo = __float2bfloat16(v - __bfloat162float(hi));
        long long base = (long long)(n0 + n) * GKK + k0;
        g_B[base + tx]        = hi;
        g_B[base + 512 + tx]  = hi;
        g_B[base + 1024 + tx] = lo;
    }
}

// ---------------------------------------------------------------------------
// init: transpose hidden [B,H] -> g_hp[0] [H,B]
// ---------------------------------------------------------------------------
__global__ void init_h_kernel(const float* __restrict__ hidden) {
    int i = blockIdx.x * blockDim.x + threadIdx.x;
    if (i < BB * HH) {
        int b = i / HH;
        int u = i - b * HH;
        g_hp[0][u * BB + b] = hidden[i];
    }
}

// ---------------------------------------------------------------------------
// Generic HMMA bf16 GEMM: C[M,N] = A[M,K] @ B[N,K]^T + bias[N]
// CTA 128x128, 256 thr (4m x 2n warps, warp tile 32x64), 4-stage, 2 CTA/SM.
// K must be a multiple of 32; grid = (M/128, N/128).
// ---------------------------------------------------------------------------
__global__ void __launch_bounds__(OTHREADS, 2)
hmma_gemm(const __nv_bfloat16* __restrict__ A, const __nv_bfloat16* __restrict__ B,
          const float* __restrict__ bias, float* __restrict__ C,
          int N, int K) {
    extern __shared__ char smem[];
    const int tid  = threadIdx.x;
    const int lane = tid & 31;
    const int wid  = tid >> 5;         // 0..7
    const int wm   = wid & 3;          // m offset wm*32
    const int wn   = wid >> 2;         // n offset wn*64
    const int m0 = blockIdx.x * OBM;
    const int n0 = blockIdx.y * OBN;
    const uint32_t sbase = smem_u32(smem);

    auto load_stage = [&](int s, int kt) {
        uint32_t sA = sbase + s * STAGE_BYTES;
        uint32_t sB = sA + A_ST_BYTES;
        long long k0 = (long long)kt * OBK;
#pragma unroll
        for (int i = 0; i < 2; i++) {
            int idx = tid + i * 256;
            int r = idx >> 2, ch = idx & 3;
            cp_async16(sA + r * 80 + ch * 16,
                       A + (long long)(m0 + r) * K + k0 + ch * 8);
        }
#pragma unroll
        for (int i = 0; i < 2; i++) {
            int idx = tid + i * 256;
            int r = idx >> 2, ch = idx & 3;
            cp_async16(sB + r * 80 + ch * 16,
                       B + (long long)(n0 + r) * K + k0 + ch * 8);
        }
        asm volatile("cp.async.commit_group;" ::: "memory");
    };

    float acc[2][8][4];
#pragma unroll
    for (int i = 0; i < 2; i++)
#pragma unroll
        for (int j = 0; j < 8; j++)
#pragma unroll
            for (int q = 0; q < 4; q++) acc[i][j][q] = 0.f;

    const int KT = K / OBK;
#pragma unroll
    for (int s = 0; s < OSTAGES - 1; s++)
        if (s < KT) load_stage(s, s);

    for (int kt = 0; kt < KT; kt++) {
        asm volatile("cp.async.wait_group %0;" :: "n"(OSTAGES - 2));
        __syncthreads();
        if (kt + OSTAGES - 1 < KT)
            load_stage((kt + OSTAGES - 1) % OSTAGES, kt + OSTAGES - 1);

        uint32_t sA = sbase + (kt % OSTAGES) * STAGE_BYTES;
        uint32_t sB = sA + A_ST_BYTES;
        const int krow = lane & 15;
#pragma unroll
        for (int ks = 0; ks < 2; ks++) {
            const int kcolb = (ks * 16 + (lane >> 4) * 8) * 2;
            uint32_t a[2][4], bb[4][4];
#pragma unroll
            for (int mt = 0; mt < 2; mt++) {
                uint32_t addr = sA + (wm * 32 + mt * 16 + krow) * 80 + kcolb;
                asm volatile("ldmatrix.sync.aligned.m8n8.x4.shared.b16 {%0,%1,%2,%3}, [%4];"
                    : "=r"(a[mt][0]), "=r"(a[mt][1]), "=r"(a[mt][2]), "=r"(a[mt][3])
                    : "r"(addr));
            }
#pragma unroll
            for (int np = 0; np < 4; np++) {
                uint32_t addr = sB + (wn * 64 + np * 16 + krow) * 80 + kcolb;
                asm volatile("ldmatrix.sync.aligned.m8n8.x4.shared.b16 {%0,%1,%2,%3}, [%4];"
                    : "=r"(bb[np][0]), "=r"(bb[np][1]), "=r"(bb[np][2]), "=r"(bb[np][3])
                    : "r"(addr));
            }
#pragma unroll
            for (int mt = 0; mt < 2; mt++)
#pragma unroll
                for (int nt = 0; nt < 8; nt++) {
                    uint32_t b0 = bb[nt >> 1][nt & 1];
                    uint32_t b1 = bb[nt >> 1][(nt & 1) + 2];
                    asm volatile(
                        "mma.sync.aligned.m16n8k16.row.col.f32.bf16.bf16.f32 "
                        "{%0,%1,%2,%3}, {%4,%5,%6,%7}, {%8,%9}, {%0,%1,%2,%3};"
                        : "+f"(acc[mt][nt][0]), "+f"(acc[mt][nt][1]),
                          "+f"(acc[mt][nt][2]), "+f"(acc[mt][nt][3])
                        : "r"(a[mt][0]), "r"(a[mt][1]), "r"(a[mt][2]), "r"(a[mt][3]),
                          "r"(b0), "r"(b1));
                }
        }
    }

    const int row_b = m0 + wm * 32 + (lane >> 2);
    const int col_b = n0 + wn * 64 + (lane & 3) * 2;
#pragma unroll
    for (int nt = 0; nt < 8; nt++) {
        int col = col_b + nt * 8;
        float b0v = __ldg(bias + col);
        float b1v = __ldg(bias + col + 1);
#pragma unroll
        for (int mt = 0; mt < 2; mt++) {
            long long r0 = row_b + mt * 16;
            float2 v0 = make_float2(acc[mt][nt][0] + b0v, acc[mt][nt][1] + b1v);
            float2 v1 = make_float2(acc[mt][nt][2] + b0v, acc[mt][nt][3] + b1v);
            *(float2*)&C[r0 * N + col]       = v0;
            *(float2*)&C[(r0 + 8) * N + col] = v1;
        }
    }
}

// ---------------------------------------------------------------------------
// Persistent LSTM, register-tiled (unchanged)
// ---------------------------------------------------------------------------
__global__ void __launch_bounds__(256, 1)
lstm_persistent(const float* __restrict__ Wh, const float* __restrict__ cell,
                float* __restrict__ out) {
    extern __shared__ float sm[];
    float* sw = sm + LW_OFF;           // [512][16]
    float* sh = sm + LH_OFF;           // [512][32]
    float* sz = sm + LZ_OFF;           // [8][16][32]
    float* sc = sm + LC_OFF;           // [128]
    const uint32_t sbase = smem_u32(sm);
    const int tid = threadIdx.x;
    const int lane = tid & 31;
    const int tb = tid & 7;
    const int tc = (tid >> 3) & 3;
    const int kg = tid >> 5;
    const int u0 = blockIdx.x * 4;

    __shared__ unsigned s_gen0;
    if (tid == 0) s_gen0 = *(volatile unsigned*)&g_bar_gen;

#pragma unroll
    for (int it = 0; it < 32; it++) {
        int e = tid + it * 256;
        int k = e >> 4, c = e & 15;
        int uu = c >> 2, g = c & 3;
        sw[e] = Wh[(long long)k * G4 + g * HH + u0 + uu];
    }
    if (tid < 128) sc[tid] = cell[(tid & 31) * HH + u0 + (tid >> 5)];
    __syncthreads();
    const unsigned gen0 = s_gen0;

    for (int t = 0; t < TT; t++) {
        const float* __restrict__ hsrc = g_hp[t & 1];
        float* __restrict__ hdst       = g_hp[(t + 1) & 1];

        {
            const float* src = hsrc + kg * 64 * BB;
            uint32_t dst = sbase + (LH_OFF + kg * 64 * BB) * 4;
#pragma unroll
            for (int j = 0; j < 16; j++) {
                int e = lane + j * 32;
                cp_async16(dst + e * 16, src + e * 4);
            }
            asm volatile("cp.async.commit_group;" ::: "memory");
            asm volatile("cp.async.wait_group 0;" ::: "memory");
            __syncwarp();
        }

        float a00=0,a01=0,a02=0,a03=0, a10=0,a11=0,a12=0,a13=0;
        float a20=0,a21=0,a22=0,a23=0, a30=0,a31=0,a32=0,a33=0;
        const float* hb = sh + kg * 64 * 32 + tb * 4;
        const float* wb = sw + kg * 64 * 16 + tc * 4;
#pragma unroll 8
        for (int k = 0; k < 64; k++) {
            float4 h4 = *(const float4*)(hb + k * 32);
            float4 w4 = *(const float4*)(wb + k * 16);
            a00 += h4.x * w4.x; a01 += h4.x * w4.y; a02 += h4.x * w4.z; a03 += h4.x * w4.w;
            a10 += h4.y * w4.x; a11 += h4.y * w4.y; a12 += h4.y * w4.z; a13 += h4.y * w4.w;
            a20 += h4.z * w4.x; a21 += h4.z * w4.y; a22 += h4.z * w4.z; a23 += h4.z * w4.w;
            a30 += h4.w * w4.x; a31 += h4.w * w4.y; a32 += h4.w * w4.z; a33 += h4.w * w4.w;
        }
        {
            float* zb = sz + kg * 512 + tb * 4;
            *(float4*)(zb + (tc * 4 + 0) * 32) = make_float4(a00, a10, a20, a30);
            *(float4*)(zb + (tc * 4 + 1) * 32) = make_float4(a01, a11, a21, a31);
            *(float4*)(zb + (tc * 4 + 2) * 32) = make_float4(a02, a12, a22, a32);
            *(float4*)(zb + (tc * 4 + 3) * 32) = make_float4(a03, a13, a23, a33);
        }
        __syncthreads();

        if (tid < 128) {
            int bb = tid & 31, uu = tid >> 5;
            float z[4];
#pragma unroll
            for (int g = 0; g < 4; g++) {
                int c = uu * 4 + g;
                float s = 0.f;
#pragma unroll
                for (int q = 0; q < 8; q++) s += sz[q * 512 + c * 32 + bb];
                z[g] = s;
            }
            const float* xzr = g_xz + (long long)(bb * TT + t) * G4 + u0 + uu;
            float zi = z[0] + xzr[0 * HH];
            float zf = z[1] + xzr[1 * HH];
            float zg = z[2] + xzr[2 * HH];
            float zo = z[3] + xzr[3 * HH];
            float si = 1.f / (1.f + expf(-zi));
            float sf = 1.f / (1.f + expf(-zf));
            float so = 1.f / (1.f + expf(-zo));
            float cn = sf * sc[tid] + si * tanhf(zg);
            float hn = so * tanhf(cn);
            sc[tid] = cn;
            hdst[(u0 + uu) * BB + bb] = hn;
            __nv_bfloat16 hi = __float2bfloat16(hn);
            __nv_bfloat16 lo = __float2bfloat16(hn - __bfloat162float(hi));
            long long abase = (long long)(bb * TT + t) * GKK + u0 + uu;
            g_A[abase]        = hi;
            g_A[abase + 512]  = lo;
            g_A[abase + 1024] = hi;
            if (t == TT - 1)
                out[LOGITS_ELEMS + bb * HH + u0 + uu] = hn;
        }

        __syncthreads();
        if (tid == 0) {
            __threadfence();
            if (atomicAdd(&g_bar_cnt, 1u) == NCTA - 1) {
                *(volatile unsigned*)&g_bar_cnt = 0;
                __threadfence();
                atomicAdd(&g_bar_gen, 1u);
            } else {
                while (*(volatile unsigned*)&g_bar_gen - gen0 < (unsigned)(t + 1)) { }
            }
            __threadfence();
        }
        __syncthreads();
    }

    if (tid < 128) {
        out[LOGITS_ELEMS + BB * HH + (tid & 31) * HH + u0 + (tid >> 5)] = sc[tid];
    }
}

// ---------------------------------------------------------------------------
extern "C" void kernel_launch(void* const* d_in, const int* in_sizes, int n_in,
                              void* d_out, int out_size) {
    const int*   inputs = (const int*)  d_in[0];
    const float* hidden = (const float*)d_in[1];
    const float* cell   = (const float*)d_in[2];
    const float* emb    = (const float*)d_in[3];
    const float* Wx     = (const float*)d_in[4];
    const float* Wh     = (const float*)d_in[5];
    const float* bias   = (const float*)d_in[6];
    const float* Wout   = (const float*)d_in[7];
    const float* bout   = (const float*)d_in[8];
    float* out = (float*)d_out;

    float *pxz;
    __nv_bfloat16 *pA, *pB, *pA2, *pB2;
    cudaGetSymbolAddress((void**)&pxz, g_xz);
    cudaGetSymbolAddress((void**)&pA,  g_A);
    cudaGetSymbolAddress((void**)&pB,  g_B);
    cudaGetSymbolAddress((void**)&pA2, g_A2);
    cudaGetSymbolAddress((void**)&pB2, g_B2);

    cudaFuncSetAttribute(hmma_gemm,
                         cudaFuncAttributeMaxDynamicSharedMemorySize, OSMEM);
    cudaFuncSetAttribute(lstm_persistent,
                         cudaFuncAttributeMaxDynamicSharedMemorySize, LSMEM_BYTES);

    // 1. gather + split x -> A2
    split_x_kernel<<<(MM * XSEG + 255) / 256, 256>>>(inputs, emb);

    // 2. split + transpose W_x -> B2
    {
        dim3 grid(G4 / 32, XSEG / 32);   // (64, 10)
        split_wx_kernel<<<grid, dim3(32, 8)>>>(Wx);
    }

    // 3. init h (transposed)
    init_h_kernel<<<(BB * HH + 255) / 256, 256>>>(hidden);

    // 4. xz = A2 @ B2^T + b  (HMMA split-bf16, 4096 x 2048 x 960)
    {
        dim3 grid(MM / OBM, G4 / OBN);   // (32, 16)
        hmma_gemm<<<grid, OTHREADS, OSMEM>>>(pA2, pB2, bias, pxz, G4, XKK);
    }

    // 5. split W_out -> B (independent of LSTM)
    {
        dim3 grid(VV / 32, HH / 32);
        split_wout_kernel<<<grid, dim3(32, 8)>>>(Wout);
    }

    // 6. all 128 LSTM steps in ONE persistent launch
    lstm_persistent<<<NCTA, 256, LSMEM_BYTES>>>(Wh, cell, out);

    // 7. logits = A @ B^T + b_out  (HMMA split-bf16, 4096 x 32000 x 1536)
    {
        dim3 grid(MM / OBM, VV / OBN);   // (32, 250)
        hmma_gemm<<<grid, OTHREADS, OSMEM>>>(pA, pB, bout, out, VV, GKK);
    }
}

// round 9
// speedup vs baseline: 2.6199x; 1.2383x over previous
#include <cuda_runtime.h>
#include <cuda_bf16.h>
#include <cuda_fp16.h>
#include <math.h>
#include <cstdint>

#define BB 32
#define TT 128
#define VV 32000
#define EE 300
#define HH 512
#define G4 (4*HH)      // 2048
#define MM (BB*TT)     // 4096
#define LOGITS_ELEMS ((long long)MM * VV)   // 131072000

// out GEMM: fp16 2-term stacked K
#define OKK 1024       // 2 * 512
// xz GEMM: bf16 3-term stacked K
#define XSEG 320       // 300 padded to 320
#define XKK (3*XSEG)   // 960

// HMMA GEMM tiling (128x128, 256 thr, 4 stages, 2 CTA/SM)
#define OBM 128
#define OBN 128
#define OBK 32
#define OSTAGES 4
#define OTHREADS 256
#define A_ST_BYTES (128*80)
#define B_ST_BYTES (128*80)
#define STAGE_BYTES (A_ST_BYTES + B_ST_BYTES)   // 20480
#define OSMEM (OSTAGES*STAGE_BYTES)             // 81920

// persistent LSTM (register-tiled)
#define NCTA 128
#define LW_OFF 0                        // [512][16]  = 8192
#define LH_OFF 8192                     // [512][32]  = 16384
#define LZ_OFF (LH_OFF + 16384)         // [8][16][32]= 4096
#define LC_OFF (LZ_OFF + 4096)          // 128
#define LSMEM_FLOATS (LC_OFF + 128)     // 28800
#define LSMEM_BYTES (LSMEM_FLOATS * 4)  // 115200 B

// ---- scratch (device globals: allocation-free) ----
__device__ float g_xz[MM * G4];       // x @ W_x + b          [4096, 2048]
__device__ float g_hp[2][HH * BB];    // h ping-pong, [u][b] layout (k-major)
__device__ __half g_A[(long long)MM * OKK];           // [4096,1024]  = [Ah|Al]
__device__ __half g_B[(long long)VV * OKK];           // [32000,1024] = [Bh|Bh]
__device__ __nv_bfloat16 g_A2[(long long)MM * XKK];   // [4096,960]   = [xh|xl|xh]
__device__ __nv_bfloat16 g_B2[(long long)G4 * XKK];   // [2048,960]   = [Wh|Wh|Wl]
__device__ unsigned g_bar_cnt = 0;
__device__ unsigned g_bar_gen = 0;

// ===========================================================================
__device__ __forceinline__ uint32_t smem_u32(const void* p) {
    uint32_t a;
    asm("{ .reg .u64 t; cvta.to.shared.u64 t, %1; cvt.u32.u64 %0, t; }" : "=r"(a) : "l"(p));
    return a;
}
__device__ __forceinline__ void cp_async16(uint32_t s, const void* g) {
    asm volatile("cp.async.cg.shared.global [%0], [%1], 16;" :: "r"(s), "l"(g));
}

// ---------------------------------------------------------------------------
// gather + split: A2[m] = [xh(320) | xl(320) | xh(320)], x = emb[inputs[m]]
// ---------------------------------------------------------------------------
__global__ void split_x_kernel(const int* __restrict__ inputs,
                               const float* __restrict__ emb) {
    int i = blockIdx.x * blockDim.x + threadIdx.x;
    if (i < MM * XSEG) {
        int m = i / XSEG;
        int k = i - m * XSEG;
        float v = (k < EE) ? emb[(long long)inputs[m] * EE + k] : 0.f;
        __nv_bfloat16 hi = __float2bfloat16(v);
        __nv_bfloat16 lo = __float2bfloat16(v - __bfloat162float(hi));
        long long base = (long long)m * XKK;
        g_A2[base + k]            = hi;
        g_A2[base + XSEG + k]     = lo;
        g_A2[base + 2*XSEG + k]   = hi;
    }
}

// ---------------------------------------------------------------------------
// split + transpose W_x [300,2048] -> B2 [2048,960] = [Wh | Wh | Wl]  (bf16)
// ---------------------------------------------------------------------------
__global__ void split_wx_kernel(const float* __restrict__ W) {
    __shared__ float t[32][33];
    int n0 = blockIdx.x * 32, k0 = blockIdx.y * 32;
    int tx = threadIdx.x, ty = threadIdx.y;           // 32 x 8
#pragma unroll
    for (int i = 0; i < 4; i++) {
        int k = k0 + ty + i * 8;
        t[ty + i * 8][tx] = (k < EE) ? W[(long long)k * G4 + n0 + tx] : 0.f;
    }
    __syncthreads();
#pragma unroll
    for (int i = 0; i < 4; i++) {
        int n = ty + i * 8;
        float v = t[tx][n];
        __nv_bfloat16 hi = __float2bfloat16(v);
        __nv_bfloat16 lo = __float2bfloat16(v - __bfloat162float(hi));
        long long base = (long long)(n0 + n) * XKK + k0;
        g_B2[base + tx]            = hi;
        g_B2[base + XSEG + tx]     = hi;
        g_B2[base + 2*XSEG + tx]   = lo;
    }
}

// ---------------------------------------------------------------------------
// split + transpose W_out [512,32000] -> B [32000,1024] = [Bh | Bh]  (fp16)
// ---------------------------------------------------------------------------
__global__ void split_wout_kernel(const float* __restrict__ W) {
    __shared__ float t[32][33];
    int n0 = blockIdx.x * 32, k0 = blockIdx.y * 32;
    int tx = threadIdx.x, ty = threadIdx.y;   // 32 x 8
#pragma unroll
    for (int i = 0; i < 4; i++) {
        int k = ty + i * 8;
        t[k][tx] = W[(long long)(k0 + k) * VV + n0 + tx];
    }
    __syncthreads();
#pragma unroll
    for (int i = 0; i < 4; i++) {
        int n = ty + i * 8;
        __half hi = __float2half(t[tx][n]);
        long long base = (long long)(n0 + n) * OKK + k0;
        g_B[base + tx]       = hi;
        g_B[base + 512 + tx] = hi;
    }
}

// ---------------------------------------------------------------------------
// init: transpose hidden [B,H] -> g_hp[0] [H,B]
// ---------------------------------------------------------------------------
__global__ void init_h_kernel(const float* __restrict__ hidden) {
    int i = blockIdx.x * blockDim.x + threadIdx.x;
    if (i < BB * HH) {
        int b = i / HH;
        int u = i - b * HH;
        g_hp[0][u * BB + b] = hidden[i];
    }
}

// ---------------------------------------------------------------------------
// Generic HMMA 16-bit GEMM: C[M,N] = A[M,K] @ B[N,K]^T + bias[N]
// FP16HI=1 -> f16 inputs, FP16HI=0 -> bf16 inputs; f32 accum either way.
// CTA 128x128, 256 thr (4m x 2n warps, warp tile 32x64), 4-stage, 2 CTA/SM.
// ---------------------------------------------------------------------------
template<int FP16M>
__global__ void __launch_bounds__(OTHREADS, 2)
hmma_gemm(const uint16_t* __restrict__ A, const uint16_t* __restrict__ B,
          const float* __restrict__ bias, float* __restrict__ C,
          int N, int K) {
    extern __shared__ char smem[];
    const int tid  = threadIdx.x;
    const int lane = tid & 31;
    const int wid  = tid >> 5;
    const int wm   = wid & 3;
    const int wn   = wid >> 2;
    const int m0 = blockIdx.x * OBM;
    const int n0 = blockIdx.y * OBN;
    const uint32_t sbase = smem_u32(smem);

    auto load_stage = [&](int s, int kt) {
        uint32_t sA = sbase + s * STAGE_BYTES;
        uint32_t sB = sA + A_ST_BYTES;
        long long k0 = (long long)kt * OBK;
#pragma unroll
        for (int i = 0; i < 2; i++) {
            int idx = tid + i * 256;
            int r = idx >> 2, ch = idx & 3;
            cp_async16(sA + r * 80 + ch * 16,
                       A + (long long)(m0 + r) * K + k0 + ch * 8);
        }
#pragma unroll
        for (int i = 0; i < 2; i++) {
            int idx = tid + i * 256;
            int r = idx >> 2, ch = idx & 3;
            cp_async16(sB + r * 80 + ch * 16,
                       B + (long long)(n0 + r) * K + k0 + ch * 8);
        }
        asm volatile("cp.async.commit_group;" ::: "memory");
    };

    float acc[2][8][4];
#pragma unroll
    for (int i = 0; i < 2; i++)
#pragma unroll
        for (int j = 0; j < 8; j++)
#pragma unroll
            for (int q = 0; q < 4; q++) acc[i][j][q] = 0.f;

    const int KT = K / OBK;
#pragma unroll
    for (int s = 0; s < OSTAGES - 1; s++)
        if (s < KT) load_stage(s, s);

    for (int kt = 0; kt < KT; kt++) {
        asm volatile("cp.async.wait_group %0;" :: "n"(OSTAGES - 2));
        __syncthreads();
        if (kt + OSTAGES - 1 < KT)
            load_stage((kt + OSTAGES - 1) % OSTAGES, kt + OSTAGES - 1);

        uint32_t sA = sbase + (kt % OSTAGES) * STAGE_BYTES;
        uint32_t sB = sA + A_ST_BYTES;
        const int krow = lane & 15;
#pragma unroll
        for (int ks = 0; ks < 2; ks++) {
            const int kcolb = (ks * 16 + (lane >> 4) * 8) * 2;
            uint32_t a[2][4], bb[4][4];
#pragma unroll
            for (int mt = 0; mt < 2; mt++) {
                uint32_t addr = sA + (wm * 32 + mt * 16 + krow) * 80 + kcolb;
                asm volatile("ldmatrix.sync.aligned.m8n8.x4.shared.b16 {%0,%1,%2,%3}, [%4];"
                    : "=r"(a[mt][0]), "=r"(a[mt][1]), "=r"(a[mt][2]), "=r"(a[mt][3])
                    : "r"(addr));
            }
#pragma unroll
            for (int np = 0; np < 4; np++) {
                uint32_t addr = sB + (wn * 64 + np * 16 + krow) * 80 + kcolb;
                asm volatile("ldmatrix.sync.aligned.m8n8.x4.shared.b16 {%0,%1,%2,%3}, [%4];"
                    : "=r"(bb[np][0]), "=r"(bb[np][1]), "=r"(bb[np][2]), "=r"(bb[np][3])
                    : "r"(addr));
            }
#pragma unroll
            for (int mt = 0; mt < 2; mt++)
#pragma unroll
                for (int nt = 0; nt < 8; nt++) {
                    uint32_t b0 = bb[nt >> 1][nt & 1];
                    uint32_t b1 = bb[nt >> 1][(nt & 1) + 2];
                    if (FP16M) {
                        asm volatile(
                            "mma.sync.aligned.m16n8k16.row.col.f32.f16.f16.f32 "
                            "{%0,%1,%2,%3}, {%4,%5,%6,%7}, {%8,%9}, {%0,%1,%2,%3};"
                            : "+f"(acc[mt][nt][0]), "+f"(acc[mt][nt][1]),
                              "+f"(acc[mt][nt][2]), "+f"(acc[mt][nt][3])
                            : "r"(a[mt][0]), "r"(a[mt][1]), "r"(a[mt][2]), "r"(a[mt][3]),
                              "r"(b0), "r"(b1));
                    } else {
                        asm volatile(
                            "mma.sync.aligned.m16n8k16.row.col.f32.bf16.bf16.f32 "
                            "{%0,%1,%2,%3}, {%4,%5,%6,%7}, {%8,%9}, {%0,%1,%2,%3};"
                            : "+f"(acc[mt][nt][0]), "+f"(acc[mt][nt][1]),
                              "+f"(acc[mt][nt][2]), "+f"(acc[mt][nt][3])
                            : "r"(a[mt][0]), "r"(a[mt][1]), "r"(a[mt][2]), "r"(a[mt][3]),
                              "r"(b0), "r"(b1));
                    }
                }
        }
    }

    const int row_b = m0 + wm * 32 + (lane >> 2);
    const int col_b = n0 + wn * 64 + (lane & 3) * 2;
#pragma unroll
    for (int nt = 0; nt < 8; nt++) {
        int col = col_b + nt * 8;
        float b0v = __ldg(bias + col);
        float b1v = __ldg(bias + col + 1);
#pragma unroll
        for (int mt = 0; mt < 2; mt++) {
            long long r0 = row_b + mt * 16;
            float2 v0 = make_float2(acc[mt][nt][0] + b0v, acc[mt][nt][1] + b1v);
            float2 v1 = make_float2(acc[mt][nt][2] + b0v, acc[mt][nt][3] + b1v);
            *(float2*)&C[r0 * N + col]       = v0;
            *(float2*)&C[(r0 + 8) * N + col] = v1;
        }
    }
}

// ---------------------------------------------------------------------------
// Persistent LSTM, register-tiled; epilogue writes fp16 [Ah|Al]
// ---------------------------------------------------------------------------
__global__ void __launch_bounds__(256, 1)
lstm_persistent(const float* __restrict__ Wh, const float* __restrict__ cell,
                float* __restrict__ out) {
    extern __shared__ float sm[];
    float* sw = sm + LW_OFF;           // [512][16]
    float* sh = sm + LH_OFF;           // [512][32]
    float* sz = sm + LZ_OFF;           // [8][16][32]
    float* sc = sm + LC_OFF;           // [128]
    const uint32_t sbase = smem_u32(sm);
    const int tid = threadIdx.x;
    const int lane = tid & 31;
    const int tb = tid & 7;
    const int tc = (tid >> 3) & 3;
    const int kg = tid >> 5;
    const int u0 = blockIdx.x * 4;

    __shared__ unsigned s_gen0;
    if (tid == 0) s_gen0 = *(volatile unsigned*)&g_bar_gen;

#pragma unroll
    for (int it = 0; it < 32; it++) {
        int e = tid + it * 256;
        int k = e >> 4, c = e & 15;
        int uu = c >> 2, g = c & 3;
        sw[e] = Wh[(long long)k * G4 + g * HH + u0 + uu];
    }
    if (tid < 128) sc[tid] = cell[(tid & 31) * HH + u0 + (tid >> 5)];
    __syncthreads();
    const unsigned gen0 = s_gen0;

    for (int t = 0; t < TT; t++) {
        const float* __restrict__ hsrc = g_hp[t & 1];
        float* __restrict__ hdst       = g_hp[(t + 1) & 1];

        {
            const float* src = hsrc + kg * 64 * BB;
            uint32_t dst = sbase + (LH_OFF + kg * 64 * BB) * 4;
#pragma unroll
            for (int j = 0; j < 16; j++) {
                int e = lane + j * 32;
                cp_async16(dst + e * 16, src + e * 4);
            }
            asm volatile("cp.async.commit_group;" ::: "memory");
            asm volatile("cp.async.wait_group 0;" ::: "memory");
            __syncwarp();
        }

        float a00=0,a01=0,a02=0,a03=0, a10=0,a11=0,a12=0,a13=0;
        float a20=0,a21=0,a22=0,a23=0, a30=0,a31=0,a32=0,a33=0;
        const float* hb = sh + kg * 64 * 32 + tb * 4;
        const float* wb = sw + kg * 64 * 16 + tc * 4;
#pragma unroll 8
        for (int k = 0; k < 64; k++) {
            float4 h4 = *(const float4*)(hb + k * 32);
            float4 w4 = *(const float4*)(wb + k * 16);
            a00 += h4.x * w4.x; a01 += h4.x * w4.y; a02 += h4.x * w4.z; a03 += h4.x * w4.w;
            a10 += h4.y * w4.x; a11 += h4.y * w4.y; a12 += h4.y * w4.z; a13 += h4.y * w4.w;
            a20 += h4.z * w4.x; a21 += h4.z * w4.y; a22 += h4.z * w4.z; a23 += h4.z * w4.w;
            a30 += h4.w * w4.x; a31 += h4.w * w4.y; a32 += h4.w * w4.z; a33 += h4.w * w4.w;
        }
        {
            float* zb = sz + kg * 512 + tb * 4;
            *(float4*)(zb + (tc * 4 + 0) * 32) = make_float4(a00, a10, a20, a30);
            *(float4*)(zb + (tc * 4 + 1) * 32) = make_float4(a01, a11, a21, a31);
            *(float4*)(zb + (tc * 4 + 2) * 32) = make_float4(a02, a12, a22, a32);
            *(float4*)(zb + (tc * 4 + 3) * 32) = make_float4(a03, a13, a23, a33);
        }
        __syncthreads();

        if (tid < 128) {
            int bb = tid & 31, uu = tid >> 5;
            float z[4];
#pragma unroll
            for (int g = 0; g < 4; g++) {
                int c = uu * 4 + g;
                float s = 0.f;
#pragma unroll
                for (int q = 0; q < 8; q++) s += sz[q * 512 + c * 32 + bb];
                z[g] = s;
            }
            const float* xzr = g_xz + (long long)(bb * TT + t) * G4 + u0 + uu;
            float zi = z[0] + xzr[0 * HH];
            float zf = z[1] + xzr[1 * HH];
            float zg = z[2] + xzr[2 * HH];
            float zo = z[3] + xzr[3 * HH];
            float si = 1.f / (1.f + expf(-zi));
            float sf = 1.f / (1.f + expf(-zf));
            float so = 1.f / (1.f + expf(-zo));
            float cn = sf * sc[tid] + si * tanhf(zg);
            float hn = so * tanhf(cn);
            sc[tid] = cn;
            hdst[(u0 + uu) * BB + bb] = hn;
            // fp16 2-term split write: A = [Ah | Al]
            __half hi = __float2half(hn);
            __half lo = __float2half(hn - __half2float(hi));
            long long abase = (long long)(bb * TT + t) * OKK + u0 + uu;
            g_A[abase]       = hi;
            g_A[abase + 512] = lo;
            if (t == TT - 1)
                out[LOGITS_ELEMS + bb * HH + u0 + uu] = hn;
        }

        __syncthreads();
        if (tid == 0) {
            __threadfence();
            if (atomicAdd(&g_bar_cnt, 1u) == NCTA - 1) {
                *(volatile unsigned*)&g_bar_cnt = 0;
                __threadfence();
                atomicAdd(&g_bar_gen, 1u);
            } else {
                while (*(volatile unsigned*)&g_bar_gen - gen0 < (unsigned)(t + 1)) { }
            }
            __threadfence();
        }
        __syncthreads();
    }

    if (tid < 128) {
        out[LOGITS_ELEMS + BB * HH + (tid & 31) * HH + u0 + (tid >> 5)] = sc[tid];
    }
}

// ---------------------------------------------------------------------------
extern "C" void kernel_launch(void* const* d_in, const int* in_sizes, int n_in,
                              void* d_out, int out_size) {
    const int*   inputs = (const int*)  d_in[0];
    const float* hidden = (const float*)d_in[1];
    const float* cell   = (const float*)d_in[2];
    const float* emb    = (const float*)d_in[3];
    const float* Wx     = (const float*)d_in[4];
    const float* Wh     = (const float*)d_in[5];
    const float* bias   = (const float*)d_in[6];
    const float* Wout   = (const float*)d_in[7];
    const float* bout   = (const float*)d_in[8];
    float* out = (float*)d_out;

    float *pxz;
    __half *pA, *pB;
    __nv_bfloat16 *pA2, *pB2;
    cudaGetSymbolAddress((void**)&pxz, g_xz);
    cudaGetSymbolAddress((void**)&pA,  g_A);
    cudaGetSymbolAddress((void**)&pB,  g_B);
    cudaGetSymbolAddress((void**)&pA2, g_A2);
    cudaGetSymbolAddress((void**)&pB2, g_B2);

    cudaFuncSetAttribute(hmma_gemm<0>,
                         cudaFuncAttributeMaxDynamicSharedMemorySize, OSMEM);
    cudaFuncSetAttribute(hmma_gemm<1>,
                         cudaFuncAttributeMaxDynamicSharedMemorySize, OSMEM);
    cudaFuncSetAttribute(lstm_persistent,
                         cudaFuncAttributeMaxDynamicSharedMemorySize, LSMEM_BYTES);

    // 1. gather + split x -> A2 (bf16 3-term)
    split_x_kernel<<<(MM * XSEG + 255) / 256, 256>>>(inputs, emb);

    // 2. split + transpose W_x -> B2 (bf16 3-term)
    {
        dim3 grid(G4 / 32, XSEG / 32);   // (64, 10)
        split_wx_kernel<<<grid, dim3(32, 8)>>>(Wx);
    }

    // 3. init h (transposed)
    init_h_kernel<<<(BB * HH + 255) / 256, 256>>>(hidden);

    // 4. xz = A2 @ B2^T + b  (bf16 HMMA, 4096 x 2048 x 960)
    {
        dim3 grid(MM / OBM, G4 / OBN);   // (32, 16)
        hmma_gemm<0><<<grid, OTHREADS, OSMEM>>>((const uint16_t*)pA2,
                                                (const uint16_t*)pB2,
                                                bias, pxz, G4, XKK);
    }

    // 5. split W_out -> B (fp16 2-term, independent of LSTM)
    {
        dim3 grid(VV / 32, HH / 32);
        split_wout_kernel<<<grid, dim3(32, 8)>>>(Wout);
    }

    // 6. all 128 LSTM steps in ONE persistent launch (writes fp16 A split)
    lstm_persistent<<<NCTA, 256, LSMEM_BYTES>>>(Wh, cell, out);

    // 7. logits = A @ B^T + b_out  (fp16 HMMA, 4096 x 32000 x 1024)
    {
        dim3 grid(MM / OBM, VV / OBN);   // (32, 250)
        hmma_gemm<1><<<grid, OTHREADS, OSMEM>>>((const uint16_t*)pA,
                                                (const uint16_t*)pB,
                                                bout, out, VV, OKK);
    }
}

// round 10
// speedup vs baseline: 2.7652x; 1.0555x over previous
#include <cuda_runtime.h>
#include <cuda_bf16.h>
#include <cuda_fp16.h>
#include <math.h>
#include <cstdint>

#define BB 32
#define TT 128
#define VV 32000
#define EE 300
#define HH 512
#define G4 (4*HH)      // 2048
#define MM (BB*TT)     // 4096
#define LOGITS_ELEMS ((long long)MM * VV)   // 131072000

// out GEMM: fp16 2-term stacked K
#define OKK 1024       // 2 * 512
// xz GEMM: bf16 3-term stacked K
#define XSEG 320       // 300 padded to 320
#define XKK (3*XSEG)   // 960

// HMMA GEMM tiling (128x128, BK=64, 256 thr, 3 stages, 2 CTA/SM)
#define OBM 128
#define OBN 128
#define OBK 64
#define OSTAGES 3
#define OTHREADS 256
#define ROWB 144                               // 64 halves + 8 pad = 144 B
#define A_ST_BYTES (128*ROWB)                  // 18432
#define B_ST_BYTES (128*ROWB)
#define STAGE_BYTES (A_ST_BYTES + B_ST_BYTES)  // 36864
#define OSMEM (OSTAGES*STAGE_BYTES)            // 110592

// persistent LSTM (register-tiled)
#define NCTA 128
#define LW_OFF 0                        // [512][16]  = 8192
#define LH_OFF 8192                     // [512][32]  = 16384
#define LZ_OFF (LH_OFF + 16384)         // [8][16][32]= 4096
#define LC_OFF (LZ_OFF + 4096)          // 128
#define LSMEM_FLOATS (LC_OFF + 128)     // 28800
#define LSMEM_BYTES (LSMEM_FLOATS * 4)  // 115200 B

// ---- scratch (device globals: allocation-free) ----
__device__ float g_xz[MM * G4];       // x @ W_x + b          [4096, 2048]
__device__ float g_hp[2][HH * BB];    // h ping-pong, [u][b] layout (k-major)
__device__ __half g_A[(long long)MM * OKK];           // [4096,1024]  = [Ah|Al]
__device__ __half g_B[(long long)VV * OKK];           // [32000,1024] = [Bh|Bh]
__device__ __nv_bfloat16 g_A2[(long long)MM * XKK];   // [4096,960]   = [xh|xl|xh]
__device__ __nv_bfloat16 g_B2[(long long)G4 * XKK];   // [2048,960]   = [Wh|Wh|Wl]
__device__ unsigned g_bar_cnt = 0;
__device__ unsigned g_bar_gen = 0;

// ===========================================================================
__device__ __forceinline__ uint32_t smem_u32(const void* p) {
    uint32_t a;
    asm("{ .reg .u64 t; cvta.to.shared.u64 t, %1; cvt.u32.u64 %0, t; }" : "=r"(a) : "l"(p));
    return a;
}
__device__ __forceinline__ void cp_async16(uint32_t s, const void* g) {
    asm volatile("cp.async.cg.shared.global [%0], [%1], 16;" :: "r"(s), "l"(g));
}

// ---------------------------------------------------------------------------
// gather + split: A2[m] = [xh(320) | xl(320) | xh(320)], x = emb[inputs[m]]
// ---------------------------------------------------------------------------
__global__ void split_x_kernel(const int* __restrict__ inputs,
                               const float* __restrict__ emb) {
    int i = blockIdx.x * blockDim.x + threadIdx.x;
    if (i < MM * XSEG) {
        int m = i / XSEG;
        int k = i - m * XSEG;
        float v = (k < EE) ? emb[(long long)inputs[m] * EE + k] : 0.f;
        __nv_bfloat16 hi = __float2bfloat16(v);
        __nv_bfloat16 lo = __float2bfloat16(v - __bfloat162float(hi));
        long long base = (long long)m * XKK;
        g_A2[base + k]            = hi;
        g_A2[base + XSEG + k]     = lo;
        g_A2[base + 2*XSEG + k]   = hi;
    }
}

// ---------------------------------------------------------------------------
// split + transpose W_x [300,2048] -> B2 [2048,960] = [Wh | Wh | Wl]  (bf16)
// ---------------------------------------------------------------------------
__global__ void split_wx_kernel(const float* __restrict__ W) {
    __shared__ float t[32][33];
    int n0 = blockIdx.x * 32, k0 = blockIdx.y * 32;
    int tx = threadIdx.x, ty = threadIdx.y;           // 32 x 8
#pragma unroll
    for (int i = 0; i < 4; i++) {
        int k = k0 + ty + i * 8;
        t[ty + i * 8][tx] = (k < EE) ? W[(long long)k * G4 + n0 + tx] : 0.f;
    }
    __syncthreads();
#pragma unroll
    for (int i = 0; i < 4; i++) {
        int n = ty + i * 8;
        float v = t[tx][n];
        __nv_bfloat16 hi = __float2bfloat16(v);
        __nv_bfloat16 lo = __float2bfloat16(v - __bfloat162float(hi));
        long long base = (long long)(n0 + n) * XKK + k0;
        g_B2[base + tx]            = hi;
        g_B2[base + XSEG + tx]     = hi;
        g_B2[base + 2*XSEG + tx]   = lo;
    }
}

// ---------------------------------------------------------------------------
// split + transpose W_out [512,32000] -> B [32000,1024] = [Bh | Bh]  (fp16)
// ---------------------------------------------------------------------------
__global__ void split_wout_kernel(const float* __restrict__ W) {
    __shared__ float t[32][33];
    int n0 = blockIdx.x * 32, k0 = blockIdx.y * 32;
    int tx = threadIdx.x, ty = threadIdx.y;   // 32 x 8
#pragma unroll
    for (int i = 0; i < 4; i++) {
        int k = ty + i * 8;
        t[k][tx] = W[(long long)(k0 + k) * VV + n0 + tx];
    }
    __syncthreads();
#pragma unroll
    for (int i = 0; i < 4; i++) {
        int n = ty + i * 8;
        __half hi = __float2half(t[tx][n]);
        long long base = (long long)(n0 + n) * OKK + k0;
        g_B[base + tx]       = hi;
        g_B[base + 512 + tx] = hi;
    }
}

// ---------------------------------------------------------------------------
// init: transpose hidden [B,H] -> g_hp[0] [H,B]
// ---------------------------------------------------------------------------
__global__ void init_h_kernel(const float* __restrict__ hidden) {
    int i = blockIdx.x * blockDim.x + threadIdx.x;
    if (i < BB * HH) {
        int b = i / HH;
        int u = i - b * HH;
        g_hp[0][u * BB + b] = hidden[i];
    }
}

// ---------------------------------------------------------------------------
// Generic HMMA 16-bit GEMM: C[M,N] = A[M,K] @ B[N,K]^T + bias[N]
// FP16M=1 -> f16 inputs, FP16M=0 -> bf16 inputs; f32 accum either way.
// CTA 128x128, BK=64, 256 thr (4m x 2n warps), 3 stages, 2 CTA/SM.
// K must be a multiple of 64; grid = (M/128, N/128).
// ---------------------------------------------------------------------------
template<int FP16M>
__global__ void __launch_bounds__(OTHREADS, 2)
hmma_gemm(const uint16_t* __restrict__ A, const uint16_t* __restrict__ B,
          const float* __restrict__ bias, float* __restrict__ C,
          int N, int K) {
    extern __shared__ char smem[];
    const int tid  = threadIdx.x;
    const int lane = tid & 31;
    const int wid  = tid >> 5;
    const int wm   = wid & 3;
    const int wn   = wid >> 2;
    const int m0 = blockIdx.x * OBM;
    const int n0 = blockIdx.y * OBN;
    const uint32_t sbase = smem_u32(smem);

    auto load_stage = [&](int s, int kt) {
        uint32_t sA = sbase + s * STAGE_BYTES;
        uint32_t sB = sA + A_ST_BYTES;
        long long k0 = (long long)kt * OBK;
        // A: 128 rows x 8 chunks of 16B = 1024 chunks (4 iters of 256 thr)
#pragma unroll
        for (int i = 0; i < 4; i++) {
            int idx = tid + i * 256;
            int r = idx >> 3, ch = idx & 7;
            cp_async16(sA + r * ROWB + ch * 16,
                       A + (long long)(m0 + r) * K + k0 + ch * 8);
        }
#pragma unroll
        for (int i = 0; i < 4; i++) {
            int idx = tid + i * 256;
            int r = idx >> 3, ch = idx & 7;
            cp_async16(sB + r * ROWB + ch * 16,
                       B + (long long)(n0 + r) * K + k0 + ch * 8);
        }
        asm volatile("cp.async.commit_group;" ::: "memory");
    };

    float acc[2][8][4];
#pragma unroll
    for (int i = 0; i < 2; i++)
#pragma unroll
        for (int j = 0; j < 8; j++)
#pragma unroll
            for (int q = 0; q < 4; q++) acc[i][j][q] = 0.f;

    const int KT = K / OBK;
#pragma unroll
    for (int s = 0; s < OSTAGES - 1; s++)
        if (s < KT) load_stage(s, s);

    for (int kt = 0; kt < KT; kt++) {
        asm volatile("cp.async.wait_group %0;" :: "n"(OSTAGES - 2));
        __syncthreads();
        if (kt + OSTAGES - 1 < KT)
            load_stage((kt + OSTAGES - 1) % OSTAGES, kt + OSTAGES - 1);

        uint32_t sA = sbase + (kt % OSTAGES) * STAGE_BYTES;
        uint32_t sB = sA + A_ST_BYTES;
        const int krow = lane & 15;
#pragma unroll
        for (int ks = 0; ks < 4; ks++) {
            const int kcolb = (ks * 16 + (lane >> 4) * 8) * 2;   // byte offset
            uint32_t a[2][4], bb[4][4];
#pragma unroll
            for (int mt = 0; mt < 2; mt++) {
                uint32_t addr = sA + (wm * 32 + mt * 16 + krow) * ROWB + kcolb;
                asm("ldmatrix.sync.aligned.m8n8.x4.shared.b16 {%0,%1,%2,%3}, [%4];"
                    : "=r"(a[mt][0]), "=r"(a[mt][1]), "=r"(a[mt][2]), "=r"(a[mt][3])
                    : "r"(addr) : "memory");
            }
#pragma unroll
            for (int np = 0; np < 4; np++) {
                uint32_t addr = sB + (wn * 64 + np * 16 + krow) * ROWB + kcolb;
                asm("ldmatrix.sync.aligned.m8n8.x4.shared.b16 {%0,%1,%2,%3}, [%4];"
                    : "=r"(bb[np][0]), "=r"(bb[np][1]), "=r"(bb[np][2]), "=r"(bb[np][3])
                    : "r"(addr) : "memory");
            }
#pragma unroll
            for (int mt = 0; mt < 2; mt++)
#pragma unroll
                for (int nt = 0; nt < 8; nt++) {
                    uint32_t b0 = bb[nt >> 1][nt & 1];
                    uint32_t b1 = bb[nt >> 1][(nt & 1) + 2];
                    if (FP16M) {
                        asm("mma.sync.aligned.m16n8k16.row.col.f32.f16.f16.f32 "
                            "{%0,%1,%2,%3}, {%4,%5,%6,%7}, {%8,%9}, {%0,%1,%2,%3};"
                            : "+f"(acc[mt][nt][0]), "+f"(acc[mt][nt][1]),
                              "+f"(acc[mt][nt][2]), "+f"(acc[mt][nt][3])
                            : "r"(a[mt][0]), "r"(a[mt][1]), "r"(a[mt][2]), "r"(a[mt][3]),
                              "r"(b0), "r"(b1));
                    } else {
                        asm("mma.sync.aligned.m16n8k16.row.col.f32.bf16.bf16.f32 "
                            "{%0,%1,%2,%3}, {%4,%5,%6,%7}, {%8,%9}, {%0,%1,%2,%3};"
                            : "+f"(acc[mt][nt][0]), "+f"(acc[mt][nt][1]),
                              "+f"(acc[mt][nt][2]), "+f"(acc[mt][nt][3])
                            : "r"(a[mt][0]), "r"(a[mt][1]), "r"(a[mt][2]), "r"(a[mt][3]),
                              "r"(b0), "r"(b1));
                    }
                }
        }
    }

    const int row_b = m0 + wm * 32 + (lane >> 2);
    const int col_b = n0 + wn * 64 + (lane & 3) * 2;
#pragma unroll
    for (int nt = 0; nt < 8; nt++) {
        int col = col_b + nt * 8;
        float b0v = __ldg(bias + col);
        float b1v = __ldg(bias + col + 1);
#pragma unroll
        for (int mt = 0; mt < 2; mt++) {
            long long r0 = row_b + mt * 16;
            float2 v0 = make_float2(acc[mt][nt][0] + b0v, acc[mt][nt][1] + b1v);
            float2 v1 = make_float2(acc[mt][nt][2] + b0v, acc[mt][nt][3] + b1v);
            *(float2*)&C[r0 * N + col]       = v0;
            *(float2*)&C[(r0 + 8) * N + col] = v1;
        }
    }
}

// ---------------------------------------------------------------------------
// Persistent LSTM, register-tiled; epilogue writes fp16 [Ah|Al]
// ---------------------------------------------------------------------------
__global__ void __launch_bounds__(256, 1)
lstm_persistent(const float* __restrict__ Wh, const float* __restrict__ cell,
                float* __restrict__ out) {
    extern __shared__ float sm[];
    float* sw = sm + LW_OFF;           // [512][16]
    float* sh = sm + LH_OFF;           // [512][32]
    float* sz = sm + LZ_OFF;           // [8][16][32]
    float* sc = sm + LC_OFF;           // [128]
    const uint32_t sbase = smem_u32(sm);
    const int tid = threadIdx.x;
    const int lane = tid & 31;
    const int tb = tid & 7;
    const int tc = (tid >> 3) & 3;
    const int kg = tid >> 5;
    const int u0 = blockIdx.x * 4;

    __shared__ unsigned s_gen0;
    if (tid == 0) s_gen0 = *(volatile unsigned*)&g_bar_gen;

#pragma unroll
    for (int it = 0; it < 32; it++) {
        int e = tid + it * 256;
        int k = e >> 4, c = e & 15;
        int uu = c >> 2, g = c & 3;
        sw[e] = Wh[(long long)k * G4 + g * HH + u0 + uu];
    }
    if (tid < 128) sc[tid] = cell[(tid & 31) * HH + u0 + (tid >> 5)];
    __syncthreads();
    const unsigned gen0 = s_gen0;

    for (int t = 0; t < TT; t++) {
        const float* __restrict__ hsrc = g_hp[t & 1];
        float* __restrict__ hdst       = g_hp[(t + 1) & 1];

        {
            const float* src = hsrc + kg * 64 * BB;
            uint32_t dst = sbase + (LH_OFF + kg * 64 * BB) * 4;
#pragma unroll
            for (int j = 0; j < 16; j++) {
                int e = lane + j * 32;
                cp_async16(dst + e * 16, src + e * 4);
            }
            asm volatile("cp.async.commit_group;" ::: "memory");
            asm volatile("cp.async.wait_group 0;" ::: "memory");
            __syncwarp();
        }

        float a00=0,a01=0,a02=0,a03=0, a10=0,a11=0,a12=0,a13=0;
        float a20=0,a21=0,a22=0,a23=0, a30=0,a31=0,a32=0,a33=0;
        const float* hb = sh + kg * 64 * 32 + tb * 4;
        const float* wb = sw + kg * 64 * 16 + tc * 4;
#pragma unroll 8
        for (int k = 0; k < 64; k++) {
            float4 h4 = *(const float4*)(hb + k * 32);
            float4 w4 = *(const float4*)(wb + k * 16);
            a00 += h4.x * w4.x; a01 += h4.x * w4.y; a02 += h4.x * w4.z; a03 += h4.x * w4.w;
            a10 += h4.y * w4.x; a11 += h4.y * w4.y; a12 += h4.y * w4.z; a13 += h4.y * w4.w;
            a20 += h4.z * w4.x; a21 += h4.z * w4.y; a22 += h4.z * w4.z; a23 += h4.z * w4.w;
            a30 += h4.w * w4.x; a31 += h4.w * w4.y; a32 += h4.w * w4.z; a33 += h4.w * w4.w;
        }
        {
            float* zb = sz + kg * 512 + tb * 4;
            *(float4*)(zb + (tc * 4 + 0) * 32) = make_float4(a00, a10, a20, a30);
            *(float4*)(zb + (tc * 4 + 1) * 32) = make_float4(a01, a11, a21, a31);
            *(float4*)(zb + (tc * 4 + 2) * 32) = make_float4(a02, a12, a22, a32);
            *(float4*)(zb + (tc * 4 + 3) * 32) = make_float4(a03, a13, a23, a33);
        }
        __syncthreads();

        if (tid < 128) {
            int bb = tid & 31, uu = tid >> 5;
            float z[4];
#pragma unroll
            for (int g = 0; g < 4; g++) {
                int c = uu * 4 + g;
                float s = 0.f;
#pragma unroll
                for (int q = 0; q < 8; q++) s += sz[q * 512 + c * 32 + bb];
                z[g] = s;
            }
            const float* xzr = g_xz + (long long)(bb * TT + t) * G4 + u0 + uu;
            float zi = z[0] + xzr[0 * HH];
            float zf = z[1] + xzr[1 * HH];
            float zg = z[2] + xzr[2 * HH];
            float zo = z[3] + xzr[3 * HH];
            float si = 1.f / (1.f + expf(-zi));
            float sf = 1.f / (1.f + expf(-zf));
            float so = 1.f / (1.f + expf(-zo));
            float cn = sf * sc[tid] + si * tanhf(zg);
            float hn = so * tanhf(cn);
            sc[tid] = cn;
            hdst[(u0 + uu) * BB + bb] = hn;
            __half hi = __float2half(hn);
            __half lo = __float2half(hn - __half2float(hi));
            long long abase = (long long)(bb * TT + t) * OKK + u0 + uu;
            g_A[abase]       = hi;
            g_A[abase + 512] = lo;
            if (t == TT - 1)
                out[LOGITS_ELEMS + bb * HH + u0 + uu] = hn;
        }

        __syncthreads();
        if (tid == 0) {
            __threadfence();
            if (atomicAdd(&g_bar_cnt, 1u) == NCTA - 1) {
                *(volatile unsigned*)&g_bar_cnt = 0;
                __threadfence();
                atomicAdd(&g_bar_gen, 1u);
            } else {
                while (*(volatile unsigned*)&g_bar_gen - gen0 < (unsigned)(t + 1)) { }
            }
            __threadfence();
        }
        __syncthreads();
    }

    if (tid < 128) {
        out[LOGITS_ELEMS + BB * HH + (tid & 31) * HH + u0 + (tid >> 5)] = sc[tid];
    }
}

// ---------------------------------------------------------------------------
extern "C" void kernel_launch(void* const* d_in, const int* in_sizes, int n_in,
                              void* d_out, int out_size) {
    const int*   inputs = (const int*)  d_in[0];
    const float* hidden = (const float*)d_in[1];
    const float* cell   = (const float*)d_in[2];
    const float* emb    = (const float*)d_in[3];
    const float* Wx     = (const float*)d_in[4];
    const float* Wh     = (const float*)d_in[5];
    const float* bias   = (const float*)d_in[6];
    const float* Wout   = (const float*)d_in[7];
    const float* bout   = (const float*)d_in[8];
    float* out = (float*)d_out;

    float *pxz;
    __half *pA, *pB;
    __nv_bfloat16 *pA2, *pB2;
    cudaGetSymbolAddress((void**)&pxz, g_xz);
    cudaGetSymbolAddress((void**)&pA,  g_A);
    cudaGetSymbolAddress((void**)&pB,  g_B);
    cudaGetSymbolAddress((void**)&pA2, g_A2);
    cudaGetSymbolAddress((void**)&pB2, g_B2);

    cudaFuncSetAttribute(hmma_gemm<0>,
                         cudaFuncAttributeMaxDynamicSharedMemorySize, OSMEM);
    cudaFuncSetAttribute(hmma_gemm<1>,
                         cudaFuncAttributeMaxDynamicSharedMemorySize, OSMEM);
    cudaFuncSetAttribute(lstm_persistent,
                         cudaFuncAttributeMaxDynamicSharedMemorySize, LSMEM_BYTES);

    // 1. gather + split x -> A2 (bf16 3-term)
    split_x_kernel<<<(MM * XSEG + 255) / 256, 256>>>(inputs, emb);

    // 2. split + transpose W_x -> B2 (bf16 3-term)
    {
        dim3 grid(G4 / 32, XSEG / 32);   // (64, 10)
        split_wx_kernel<<<grid, dim3(32, 8)>>>(Wx);
    }

    // 3. init h (transposed)
    init_h_kernel<<<(BB * HH + 255) / 256, 256>>>(hidden);

    // 4. xz = A2 @ B2^T + b  (bf16 HMMA, 4096 x 2048 x 960, KT=15)
    {
        dim3 grid(MM / OBM, G4 / OBN);   // (32, 16)
        hmma_gemm<0><<<grid, OTHREADS, OSMEM>>>((const uint16_t*)pA2,
                                                (const uint16_t*)pB2,
                                                bias, pxz, G4, XKK);
    }

    // 5. split W_out -> B (fp16 2-term, independent of LSTM)
    {
        dim3 grid(VV / 32, HH / 32);
        split_wout_kernel<<<grid, dim3(32, 8)>>>(Wout);
    }

    // 6. all 128 LSTM steps in ONE persistent launch (writes fp16 A split)
    lstm_persistent<<<NCTA, 256, LSMEM_BYTES>>>(Wh, cell, out);

    // 7. logits = A @ B^T + b_out  (fp16 HMMA, 4096 x 32000 x 1024, KT=16)
    {
        dim3 grid(MM / OBM, VV / OBN);   // (32, 250)
        hmma_gemm<1><<<grid, OTHREADS, OSMEM>>>((const uint16_t*)pA,
                                                (const uint16_t*)pB,
                                                bout, out, VV, OKK);
    }
}

// round 11
// speedup vs baseline: 3.5336x; 1.2779x over previous
#include <cuda_runtime.h>
#include <cuda_bf16.h>
#include <cuda_fp16.h>
#include <math.h>
#include <cstdint>

#define BB 32
#define TT 128
#define VV 32000
#define EE 300
#define HH 512
#define G4 (4*HH)      // 2048
#define MM (BB*TT)     // 4096
#define LOGITS_ELEMS ((long long)MM * VV)   // 131072000

// out GEMM: plain fp16, K = 512
#define OKK 512
// xz GEMM: bf16 3-term stacked K
#define XSEG 320       // 300 padded to 320
#define XKK (3*XSEG)   // 960

// HMMA GEMM tiling (128x128, BK=64, 256 thr, 3 stages, 2 CTA/SM)
#define OBM 128
#define OBN 128
#define OBK 64
#define OSTAGES 3
#define OTHREADS 256
#define ROWB 144                               // 64 halves + 8 pad = 144 B
#define A_ST_BYTES (128*ROWB)                  // 18432
#define B_ST_BYTES (128*ROWB)
#define STAGE_BYTES (A_ST_BYTES + B_ST_BYTES)  // 36864
#define OSMEM (OSTAGES*STAGE_BYTES)            // 110592

// persistent LSTM (register-tiled)
#define NCTA 128
#define LW_OFF 0                        // [512][16]  = 8192
#define LH_OFF 8192                     // [512][32]  = 16384
#define LZ_OFF (LH_OFF + 16384)         // [8][16][32]= 4096
#define LC_OFF (LZ_OFF + 4096)          // 128
#define LSMEM_FLOATS (LC_OFF + 128)     // 28800
#define LSMEM_BYTES (LSMEM_FLOATS * 4)  // 115200 B

// ---- scratch (device globals: allocation-free) ----
__device__ float g_xz[MM * G4];       // x @ W_x + b          [4096, 2048]
__device__ float g_hp[2][HH * BB];    // h ping-pong, [u][b] layout (k-major)
__device__ __half g_A[(long long)MM * OKK];           // [4096,512]   = Ah
__device__ __half g_B[(long long)VV * OKK];           // [32000,512]  = Bh
__device__ __nv_bfloat16 g_A2[(long long)MM * XKK];   // [4096,960]   = [xh|xl|xh]
__device__ __nv_bfloat16 g_B2[(long long)G4 * XKK];   // [2048,960]   = [Wh|Wh|Wl]
__device__ unsigned g_bar_cnt = 0;
__device__ unsigned g_bar_gen = 0;

// ===========================================================================
__device__ __forceinline__ uint32_t smem_u32(const void* p) {
    uint32_t a;
    asm("{ .reg .u64 t; cvta.to.shared.u64 t, %1; cvt.u32.u64 %0, t; }" : "=r"(a) : "l"(p));
    return a;
}
__device__ __forceinline__ void cp_async16(uint32_t s, const void* g) {
    asm volatile("cp.async.cg.shared.global [%0], [%1], 16;" :: "r"(s), "l"(g));
}

// ---------------------------------------------------------------------------
// gather + split: A2[m] = [xh(320) | xl(320) | xh(320)], x = emb[inputs[m]]
// ---------------------------------------------------------------------------
__global__ void split_x_kernel(const int* __restrict__ inputs,
                               const float* __restrict__ emb) {
    int i = blockIdx.x * blockDim.x + threadIdx.x;
    if (i < MM * XSEG) {
        int m = i / XSEG;
        int k = i - m * XSEG;
        float v = (k < EE) ? emb[(long long)inputs[m] * EE + k] : 0.f;
        __nv_bfloat16 hi = __float2bfloat16(v);
        __nv_bfloat16 lo = __float2bfloat16(v - __bfloat162float(hi));
        long long base = (long long)m * XKK;
        g_A2[base + k]            = hi;
        g_A2[base + XSEG + k]     = lo;
        g_A2[base + 2*XSEG + k]   = hi;
    }
}

// ---------------------------------------------------------------------------
// split + transpose W_x [300,2048] -> B2 [2048,960] = [Wh | Wh | Wl]  (bf16)
// ---------------------------------------------------------------------------
__global__ void split_wx_kernel(const float* __restrict__ W) {
    __shared__ float t[32][33];
    int n0 = blockIdx.x * 32, k0 = blockIdx.y * 32;
    int tx = threadIdx.x, ty = threadIdx.y;           // 32 x 8
#pragma unroll
    for (int i = 0; i < 4; i++) {
        int k = k0 + ty + i * 8;
        t[ty + i * 8][tx] = (k < EE) ? W[(long long)k * G4 + n0 + tx] : 0.f;
    }
    __syncthreads();
#pragma unroll
    for (int i = 0; i < 4; i++) {
        int n = ty + i * 8;
        float v = t[tx][n];
        __nv_bfloat16 hi = __float2bfloat16(v);
        __nv_bfloat16 lo = __float2bfloat16(v - __bfloat162float(hi));
        long long base = (long long)(n0 + n) * XKK + k0;
        g_B2[base + tx]            = hi;
        g_B2[base + XSEG + tx]     = hi;
        g_B2[base + 2*XSEG + tx]   = lo;
    }
}

// ---------------------------------------------------------------------------
// transpose + fp16 convert: W_out [512,32000] -> B [32000,512]
// ---------------------------------------------------------------------------
__global__ void split_wout_kernel(const float* __restrict__ W) {
    __shared__ float t[32][33];
    int n0 = blockIdx.x * 32, k0 = blockIdx.y * 32;
    int tx = threadIdx.x, ty = threadIdx.y;   // 32 x 8
#pragma unroll
    for (int i = 0; i < 4; i++) {
        int k = ty + i * 8;
        t[k][tx] = W[(long long)(k0 + k) * VV + n0 + tx];
    }
    __syncthreads();
#pragma unroll
    for (int i = 0; i < 4; i++) {
        int n = ty + i * 8;
        g_B[(long long)(n0 + n) * OKK + k0 + tx] = __float2half(t[tx][n]);
    }
}

// ---------------------------------------------------------------------------
// init: transpose hidden [B,H] -> g_hp[0] [H,B]
// ---------------------------------------------------------------------------
__global__ void init_h_kernel(const float* __restrict__ hidden) {
    int i = blockIdx.x * blockDim.x + threadIdx.x;
    if (i < BB * HH) {
        int b = i / HH;
        int u = i - b * HH;
        g_hp[0][u * BB + b] = hidden[i];
    }
}

// ---------------------------------------------------------------------------
// Generic HMMA 16-bit GEMM: C[M,N] = A[M,K] @ B[N,K]^T + bias[N]
// FP16M=1 -> f16 inputs, FP16M=0 -> bf16 inputs; f32 accum either way.
// CTA 128x128, BK=64, 256 thr (4m x 2n warps), 3 stages, 2 CTA/SM.
// ---------------------------------------------------------------------------
template<int FP16M>
__global__ void __launch_bounds__(OTHREADS, 2)
hmma_gemm(const uint16_t* __restrict__ A, const uint16_t* __restrict__ B,
          const float* __restrict__ bias, float* __restrict__ C,
          int N, int K) {
    extern __shared__ char smem[];
    const int tid  = threadIdx.x;
    const int lane = tid & 31;
    const int wid  = tid >> 5;
    const int wm   = wid & 3;
    const int wn   = wid >> 2;
    const int m0 = blockIdx.x * OBM;
    const int n0 = blockIdx.y * OBN;
    const uint32_t sbase = smem_u32(smem);

    auto load_stage = [&](int s, int kt) {
        uint32_t sA = sbase + s * STAGE_BYTES;
        uint32_t sB = sA + A_ST_BYTES;
        long long k0 = (long long)kt * OBK;
#pragma unroll
        for (int i = 0; i < 4; i++) {
            int idx = tid + i * 256;
            int r = idx >> 3, ch = idx & 7;
            cp_async16(sA + r * ROWB + ch * 16,
                       A + (long long)(m0 + r) * K + k0 + ch * 8);
        }
#pragma unroll
        for (int i = 0; i < 4; i++) {
            int idx = tid + i * 256;
            int r = idx >> 3, ch = idx & 7;
            cp_async16(sB + r * ROWB + ch * 16,
                       B + (long long)(n0 + r) * K + k0 + ch * 8);
        }
        asm volatile("cp.async.commit_group;" ::: "memory");
    };

    float acc[2][8][4];
#pragma unroll
    for (int i = 0; i < 2; i++)
#pragma unroll
        for (int j = 0; j < 8; j++)
#pragma unroll
            for (int q = 0; q < 4; q++) acc[i][j][q] = 0.f;

    const int KT = K / OBK;
#pragma unroll
    for (int s = 0; s < OSTAGES - 1; s++)
        if (s < KT) load_stage(s, s);

    for (int kt = 0; kt < KT; kt++) {
        asm volatile("cp.async.wait_group %0;" :: "n"(OSTAGES - 2));
        __syncthreads();
        if (kt + OSTAGES - 1 < KT)
            load_stage((kt + OSTAGES - 1) % OSTAGES, kt + OSTAGES - 1);

        uint32_t sA = sbase + (kt % OSTAGES) * STAGE_BYTES;
        uint32_t sB = sA + A_ST_BYTES;
        const int krow = lane & 15;
#pragma unroll
        for (int ks = 0; ks < 4; ks++) {
            const int kcolb = (ks * 16 + (lane >> 4) * 8) * 2;
            uint32_t a[2][4], bb[4][4];
#pragma unroll
            for (int mt = 0; mt < 2; mt++) {
                uint32_t addr = sA + (wm * 32 + mt * 16 + krow) * ROWB + kcolb;
                asm("ldmatrix.sync.aligned.m8n8.x4.shared.b16 {%0,%1,%2,%3}, [%4];"
                    : "=r"(a[mt][0]), "=r"(a[mt][1]), "=r"(a[mt][2]), "=r"(a[mt][3])
                    : "r"(addr) : "memory");
            }
#pragma unroll
            for (int np = 0; np < 4; np++) {
                uint32_t addr = sB + (wn * 64 + np * 16 + krow) * ROWB + kcolb;
                asm("ldmatrix.sync.aligned.m8n8.x4.shared.b16 {%0,%1,%2,%3}, [%4];"
                    : "=r"(bb[np][0]), "=r"(bb[np][1]), "=r"(bb[np][2]), "=r"(bb[np][3])
                    : "r"(addr) : "memory");
            }
#pragma unroll
            for (int mt = 0; mt < 2; mt++)
#pragma unroll
                for (int nt = 0; nt < 8; nt++) {
                    uint32_t b0 = bb[nt >> 1][nt & 1];
                    uint32_t b1 = bb[nt >> 1][(nt & 1) + 2];
                    if (FP16M) {
                        asm("mma.sync.aligned.m16n8k16.row.col.f32.f16.f16.f32 "
                            "{%0,%1,%2,%3}, {%4,%5,%6,%7}, {%8,%9}, {%0,%1,%2,%3};"
                            : "+f"(acc[mt][nt][0]), "+f"(acc[mt][nt][1]),
                              "+f"(acc[mt][nt][2]), "+f"(acc[mt][nt][3])
                            : "r"(a[mt][0]), "r"(a[mt][1]), "r"(a[mt][2]), "r"(a[mt][3]),
                              "r"(b0), "r"(b1));
                    } else {
                        asm("mma.sync.aligned.m16n8k16.row.col.f32.bf16.bf16.f32 "
                            "{%0,%1,%2,%3}, {%4,%5,%6,%7}, {%8,%9}, {%0,%1,%2,%3};"
                            : "+f"(acc[mt][nt][0]), "+f"(acc[mt][nt][1]),
                              "+f"(acc[mt][nt][2]), "+f"(acc[mt][nt][3])
                            : "r"(a[mt][0]), "r"(a[mt][1]), "r"(a[mt][2]), "r"(a[mt][3]),
                              "r"(b0), "r"(b1));
                    }
                }
        }
    }

    const int row_b = m0 + wm * 32 + (lane >> 2);
    const int col_b = n0 + wn * 64 + (lane & 3) * 2;
#pragma unroll
    for (int nt = 0; nt < 8; nt++) {
        int col = col_b + nt * 8;
        float b0v = __ldg(bias + col);
        float b1v = __ldg(bias + col + 1);
#pragma unroll
        for (int mt = 0; mt < 2; mt++) {
            long long r0 = row_b + mt * 16;
            float2 v0 = make_float2(acc[mt][nt][0] + b0v, acc[mt][nt][1] + b1v);
            float2 v1 = make_float2(acc[mt][nt][2] + b0v, acc[mt][nt][3] + b1v);
            *(float2*)&C[r0 * N + col]       = v0;
            *(float2*)&C[(r0 + 8) * N + col] = v1;
        }
    }
}

// ---------------------------------------------------------------------------
// Persistent LSTM, register-tiled; epilogue writes fp16 Ah
// ---------------------------------------------------------------------------
__global__ void __launch_bounds__(256, 1)
lstm_persistent(const float* __restrict__ Wh, const float* __restrict__ cell,
                float* __restrict__ out) {
    extern __shared__ float sm[];
    float* sw = sm + LW_OFF;           // [512][16]
    float* sh = sm + LH_OFF;           // [512][32]
    float* sz = sm + LZ_OFF;           // [8][16][32]
    float* sc = sm + LC_OFF;           // [128]
    const uint32_t sbase = smem_u32(sm);
    const int tid = threadIdx.x;
    const int lane = tid & 31;
    const int tb = tid & 7;
    const int tc = (tid >> 3) & 3;
    const int kg = tid >> 5;
    const int u0 = blockIdx.x * 4;

    __shared__ unsigned s_gen0;
    if (tid == 0) s_gen0 = *(volatile unsigned*)&g_bar_gen;

#pragma unroll
    for (int it = 0; it < 32; it++) {
        int e = tid + it * 256;
        int k = e >> 4, c = e & 15;
        int uu = c >> 2, g = c & 3;
        sw[e] = Wh[(long long)k * G4 + g * HH + u0 + uu];
    }
    if (tid < 128) sc[tid] = cell[(tid & 31) * HH + u0 + (tid >> 5)];
    __syncthreads();
    const unsigned gen0 = s_gen0;

    for (int t = 0; t < TT; t++) {
        const float* __restrict__ hsrc = g_hp[t & 1];
        float* __restrict__ hdst       = g_hp[(t + 1) & 1];

        {
            const float* src = hsrc + kg * 64 * BB;
            uint32_t dst = sbase + (LH_OFF + kg * 64 * BB) * 4;
#pragma unroll
            for (int j = 0; j < 16; j++) {
                int e = lane + j * 32;
                cp_async16(dst + e * 16, src + e * 4);
            }
            asm volatile("cp.async.commit_group;" ::: "memory");
            asm volatile("cp.async.wait_group 0;" ::: "memory");
            __syncwarp();
        }

        float a00=0,a01=0,a02=0,a03=0, a10=0,a11=0,a12=0,a13=0;
        float a20=0,a21=0,a22=0,a23=0, a30=0,a31=0,a32=0,a33=0;
        const float* hb = sh + kg * 64 * 32 + tb * 4;
        const float* wb = sw + kg * 64 * 16 + tc * 4;
#pragma unroll 8
        for (int k = 0; k < 64; k++) {
            float4 h4 = *(const float4*)(hb + k * 32);
            float4 w4 = *(const float4*)(wb + k * 16);
            a00 += h4.x * w4.x; a01 += h4.x * w4.y; a02 += h4.x * w4.z; a03 += h4.x * w4.w;
            a10 += h4.y * w4.x; a11 += h4.y * w4.y; a12 += h4.y * w4.z; a13 += h4.y * w4.w;
            a20 += h4.z * w4.x; a21 += h4.z * w4.y; a22 += h4.z * w4.z; a23 += h4.z * w4.w;
            a30 += h4.w * w4.x; a31 += h4.w * w4.y; a32 += h4.w * w4.z; a33 += h4.w * w4.w;
        }
        {
            float* zb = sz + kg * 512 + tb * 4;
            *(float4*)(zb + (tc * 4 + 0) * 32) = make_float4(a00, a10, a20, a30);
            *(float4*)(zb + (tc * 4 + 1) * 32) = make_float4(a01, a11, a21, a31);
            *(float4*)(zb + (tc * 4 + 2) * 32) = make_float4(a02, a12, a22, a32);
            *(float4*)(zb + (tc * 4 + 3) * 32) = make_float4(a03, a13, a23, a33);
        }
        __syncthreads();

        if (tid < 128) {
            int bb = tid & 31, uu = tid >> 5;
            float z[4];
#pragma unroll
            for (int g = 0; g < 4; g++) {
                int c = uu * 4 + g;
                float s = 0.f;
#pragma unroll
                for (int q = 0; q < 8; q++) s += sz[q * 512 + c * 32 + bb];
                z[g] = s;
            }
            const float* xzr = g_xz + (long long)(bb * TT + t) * G4 + u0 + uu;
            float zi = z[0] + xzr[0 * HH];
            float zf = z[1] + xzr[1 * HH];
            float zg = z[2] + xzr[2 * HH];
            float zo = z[3] + xzr[3 * HH];
            float si = 1.f / (1.f + expf(-zi));
            float sf = 1.f / (1.f + expf(-zf));
            float so = 1.f / (1.f + expf(-zo));
            float cn = sf * sc[tid] + si * tanhf(zg);
            float hn = so * tanhf(cn);
            sc[tid] = cn;
            hdst[(u0 + uu) * BB + bb] = hn;
            g_A[(long long)(bb * TT + t) * OKK + u0 + uu] = __float2half(hn);
            if (t == TT - 1)
                out[LOGITS_ELEMS + bb * HH + u0 + uu] = hn;
        }

        __syncthreads();
        if (tid == 0) {
            __threadfence();
            if (atomicAdd(&g_bar_cnt, 1u) == NCTA - 1) {
                *(volatile unsigned*)&g_bar_cnt = 0;
                __threadfence();
                atomicAdd(&g_bar_gen, 1u);
            } else {
                while (*(volatile unsigned*)&g_bar_gen - gen0 < (unsigned)(t + 1)) { }
            }
            __threadfence();
        }
        __syncthreads();
    }

    if (tid < 128) {
        out[LOGITS_ELEMS + BB * HH + (tid & 31) * HH + u0 + (tid >> 5)] = sc[tid];
    }
}

// ---------------------------------------------------------------------------
extern "C" void kernel_launch(void* const* d_in, const int* in_sizes, int n_in,
                              void* d_out, int out_size) {
    const int*   inputs = (const int*)  d_in[0];
    const float* hidden = (const float*)d_in[1];
    const float* cell   = (const float*)d_in[2];
    const float* emb    = (const float*)d_in[3];
    const float* Wx     = (const float*)d_in[4];
    const float* Wh     = (const float*)d_in[5];
    const float* bias   = (const float*)d_in[6];
    const float* Wout   = (const float*)d_in[7];
    const float* bout   = (const float*)d_in[8];
    float* out = (float*)d_out;

    float *pxz;
    __half *pA, *pB;
    __nv_bfloat16 *pA2, *pB2;
    cudaGetSymbolAddress((void**)&pxz, g_xz);
    cudaGetSymbolAddress((void**)&pA,  g_A);
    cudaGetSymbolAddress((void**)&pB,  g_B);
    cudaGetSymbolAddress((void**)&pA2, g_A2);
    cudaGetSymbolAddress((void**)&pB2, g_B2);

    cudaFuncSetAttribute(hmma_gemm<0>,
                         cudaFuncAttributeMaxDynamicSharedMemorySize, OSMEM);
    cudaFuncSetAttribute(hmma_gemm<1>,
                         cudaFuncAttributeMaxDynamicSharedMemorySize, OSMEM);
    cudaFuncSetAttribute(lstm_persistent,
                         cudaFuncAttributeMaxDynamicSharedMemorySize, LSMEM_BYTES);

    // 1. gather + split x -> A2 (bf16 3-term)
    split_x_kernel<<<(MM * XSEG + 255) / 256, 256>>>(inputs, emb);

    // 2. split + transpose W_x -> B2 (bf16 3-term)
    {
        dim3 grid(G4 / 32, XSEG / 32);   // (64, 10)
        split_wx_kernel<<<grid, dim3(32, 8)>>>(Wx);
    }

    // 3. init h (transposed)
    init_h_kernel<<<(BB * HH + 255) / 256, 256>>>(hidden);

    // 4. xz = A2 @ B2^T + b  (bf16 HMMA, 4096 x 2048 x 960, KT=15)
    {
        dim3 grid(MM / OBM, G4 / OBN);   // (32, 16)
        hmma_gemm<0><<<grid, OTHREADS, OSMEM>>>((const uint16_t*)pA2,
                                                (const uint16_t*)pB2,
                                                bias, pxz, G4, XKK);
    }

    // 5. transpose W_out -> B (fp16, independent of LSTM)
    {
        dim3 grid(VV / 32, HH / 32);
        split_wout_kernel<<<grid, dim3(32, 8)>>>(Wout);
    }

    // 6. all 128 LSTM steps in ONE persistent launch (writes fp16 A)
    lstm_persistent<<<NCTA, 256, LSMEM_BYTES>>>(Wh, cell, out);

    // 7. logits = A @ B^T + b_out  (fp16 HMMA, 4096 x 32000 x 512, KT=8)
    {
        dim3 grid(MM / OBM, VV / OBN);   // (32, 250)
        hmma_gemm<1><<<grid, OTHREADS, OSMEM>>>((const uint16_t*)pA,
                                                (const uint16_t*)pB,
                                                bout, out, VV, OKK);
    }
}

// round 12
// speedup vs baseline: 3.7863x; 1.0715x over previous
#include <cuda_runtime.h>
#include <cuda_bf16.h>
#include <cuda_fp16.h>
#include <math.h>
#include <cstdint>

#define BB 32
#define TT 128
#define VV 32000
#define EE 300
#define HH 512
#define G4 (4*HH)      // 2048
#define MM (BB*TT)     // 4096
#define LOGITS_ELEMS ((long long)MM * VV)   // 131072000

// out GEMM: plain fp16, K = 512
#define OKK 512
// xz GEMM: bf16 3-term stacked K
#define XSEG 320
#define XKK (3*XSEG)   // 960

// HMMA GEMM tiling (128x128, BK=64, 256 thr, 3 stages, 2 CTA/SM)
#define OBM 128
#define OBN 128
#define OBK 64
#define OSTAGES 3
#define OTHREADS 256
#define ROWB 144
#define A_ST_BYTES (128*ROWB)
#define B_ST_BYTES (128*ROWB)
#define STAGE_BYTES (A_ST_BYTES + B_ST_BYTES)  // 36864
#define OSMEM (OSTAGES*STAGE_BYTES)            // 110592

// persistent LSTM (HMMA) — byte offsets in dynamic smem
#define NCTA 128
#define RSCALE 2048.0f
#define RINV   (1.0f/2048.0f)
#define SWH_OFF 0                        // fp16 [16][1032]  (Whh | Whl', +8 pad)
#define SWH_ROWB 2064                    // 1032*2 bytes (516 words = 4 mod 32)
#define SHH_OFF 33024                    // fp16 [32][520]   hh
#define SH_ROWB 1040                     // 520*2 bytes (260 words = 4 mod 32)
#define SHL_OFF (SHH_OFF + 33280)        // 66304, fp16 [32][520] hl'
#define SZ_OFF  (SHL_OFF + 33280)        // 99584, fp32 [8][16][32]
#define SC_OFF  (SZ_OFF + 16384)         // 115968, fp32 [128]
#define L2SMEM  (SC_OFF + 512)           // 116480 bytes

// ---- scratch (device globals: allocation-free) ----
__device__ float g_xz[MM * G4];       // x @ W_x + b          [4096, 2048]
__device__ __half g_hh[2][BB * HH];   // h hi,  [b][u] fp16
__device__ __half g_hl[2][BB * HH];   // h lo * 2048, [b][u] fp16
__device__ float g_c_unused;          // (placeholder)
__device__ __half g_A[(long long)MM * OKK];           // [4096,512]   = Ah
__device__ __half g_B[(long long)VV * OKK];           // [32000,512]  = Bh
__device__ __nv_bfloat16 g_A2[(long long)MM * XKK];   // [4096,960]   = [xh|xl|xh]
__device__ __nv_bfloat16 g_B2[(long long)G4 * XKK];   // [2048,960]   = [Wh|Wh|Wl]
__device__ unsigned g_bar_cnt = 0;
__device__ unsigned g_bar_gen = 0;

// ===========================================================================
__device__ __forceinline__ uint32_t smem_u32(const void* p) {
    uint32_t a;
    asm("{ .reg .u64 t; cvta.to.shared.u64 t, %1; cvt.u32.u64 %0, t; }" : "=r"(a) : "l"(p));
    return a;
}
__device__ __forceinline__ void cp_async16(uint32_t s, const void* g) {
    asm volatile("cp.async.cg.shared.global [%0], [%1], 16;" :: "r"(s), "l"(g));
}
__device__ __forceinline__ void ldm_x4(uint32_t addr, uint32_t* r) {
    asm("ldmatrix.sync.aligned.m8n8.x4.shared.b16 {%0,%1,%2,%3}, [%4];"
        : "=r"(r[0]), "=r"(r[1]), "=r"(r[2]), "=r"(r[3]) : "r"(addr) : "memory");
}
__device__ __forceinline__ void mma_f16(float* d, const uint32_t* a,
                                        uint32_t b0, uint32_t b1) {
    asm("mma.sync.aligned.m16n8k16.row.col.f32.f16.f16.f32 "
        "{%0,%1,%2,%3}, {%4,%5,%6,%7}, {%8,%9}, {%0,%1,%2,%3};"
        : "+f"(d[0]), "+f"(d[1]), "+f"(d[2]), "+f"(d[3])
        : "r"(a[0]), "r"(a[1]), "r"(a[2]), "r"(a[3]), "r"(b0), "r"(b1));
}

// ---------------------------------------------------------------------------
// gather + split: A2[m] = [xh(320) | xl(320) | xh(320)], x = emb[inputs[m]]
// ---------------------------------------------------------------------------
__global__ void split_x_kernel(const int* __restrict__ inputs,
                               const float* __restrict__ emb) {
    int i = blockIdx.x * blockDim.x + threadIdx.x;
    if (i < MM * XSEG) {
        int m = i / XSEG;
        int k = i - m * XSEG;
        float v = (k < EE) ? emb[(long long)inputs[m] * EE + k] : 0.f;
        __nv_bfloat16 hi = __float2bfloat16(v);
        __nv_bfloat16 lo = __float2bfloat16(v - __bfloat162float(hi));
        long long base = (long long)m * XKK;
        g_A2[base + k]            = hi;
        g_A2[base + XSEG + k]     = lo;
        g_A2[base + 2*XSEG + k]   = hi;
    }
}

// ---------------------------------------------------------------------------
// split + transpose W_x [300,2048] -> B2 [2048,960] = [Wh | Wh | Wl]  (bf16)
// ---------------------------------------------------------------------------
__global__ void split_wx_kernel(const float* __restrict__ W) {
    __shared__ float t[32][33];
    int n0 = blockIdx.x * 32, k0 = blockIdx.y * 32;
    int tx = threadIdx.x, ty = threadIdx.y;           // 32 x 8
#pragma unroll
    for (int i = 0; i < 4; i++) {
        int k = k0 + ty + i * 8;
        t[ty + i * 8][tx] = (k < EE) ? W[(long long)k * G4 + n0 + tx] : 0.f;
    }
    __syncthreads();
#pragma unroll
    for (int i = 0; i < 4; i++) {
        int n = ty + i * 8;
        float v = t[tx][n];
        __nv_bfloat16 hi = __float2bfloat16(v);
        __nv_bfloat16 lo = __float2bfloat16(v - __bfloat162float(hi));
        long long base = (long long)(n0 + n) * XKK + k0;
        g_B2[base + tx]            = hi;
        g_B2[base + XSEG + tx]     = hi;
        g_B2[base + 2*XSEG + tx]   = lo;
    }
}

// ---------------------------------------------------------------------------
// transpose + fp16 convert: W_out [512,32000] -> B [32000,512]
// ---------------------------------------------------------------------------
__global__ void split_wout_kernel(const float* __restrict__ W) {
    __shared__ float t[32][33];
    int n0 = blockIdx.x * 32, k0 = blockIdx.y * 32;
    int tx = threadIdx.x, ty = threadIdx.y;   // 32 x 8
#pragma unroll
    for (int i = 0; i < 4; i++) {
        int k = ty + i * 8;
        t[k][tx] = W[(long long)(k0 + k) * VV + n0 + tx];
    }
    __syncthreads();
#pragma unroll
    for (int i = 0; i < 4; i++) {
        int n = ty + i * 8;
        g_B[(long long)(n0 + n) * OKK + k0 + tx] = __float2half(t[tx][n]);
    }
}

// ---------------------------------------------------------------------------
// init h: [b][u] fp16 split pair
// ---------------------------------------------------------------------------
__global__ void init_h_kernel(const float* __restrict__ hidden) {
    int i = blockIdx.x * blockDim.x + threadIdx.x;
    if (i < BB * HH) {
        float v = hidden[i];
        __half hh = __float2half(v);
        g_hh[0][i] = hh;
        g_hl[0][i] = __float2half((v - __half2float(hh)) * RSCALE);
    }
}

// ---------------------------------------------------------------------------
// Generic HMMA 16-bit GEMM (unchanged from R11)
// ---------------------------------------------------------------------------
template<int FP16M>
__global__ void __launch_bounds__(OTHREADS, 2)
hmma_gemm(const uint16_t* __restrict__ A, const uint16_t* __restrict__ B,
          const float* __restrict__ bias, float* __restrict__ C,
          int N, int K) {
    extern __shared__ char smem[];
    const int tid  = threadIdx.x;
    const int lane = tid & 31;
    const int wid  = tid >> 5;
    const int wm   = wid & 3;
    const int wn   = wid >> 2;
    const int m0 = blockIdx.x * OBM;
    const int n0 = blockIdx.y * OBN;
    const uint32_t sbase = smem_u32(smem);

    auto load_stage = [&](int s, int kt) {
        uint32_t sA = sbase + s * STAGE_BYTES;
        uint32_t sB = sA + A_ST_BYTES;
        long long k0 = (long long)kt * OBK;
#pragma unroll
        for (int i = 0; i < 4; i++) {
            int idx = tid + i * 256;
            int r = idx >> 3, ch = idx & 7;
            cp_async16(sA + r * ROWB + ch * 16,
                       A + (long long)(m0 + r) * K + k0 + ch * 8);
        }
#pragma unroll
        for (int i = 0; i < 4; i++) {
            int idx = tid + i * 256;
            int r = idx >> 3, ch = idx & 7;
            cp_async16(sB + r * ROWB + ch * 16,
                       B + (long long)(n0 + r) * K + k0 + ch * 8);
        }
        asm volatile("cp.async.commit_group;" ::: "memory");
    };

    float acc[2][8][4];
#pragma unroll
    for (int i = 0; i < 2; i++)
#pragma unroll
        for (int j = 0; j < 8; j++)
#pragma unroll
            for (int q = 0; q < 4; q++) acc[i][j][q] = 0.f;

    const int KT = K / OBK;
#pragma unroll
    for (int s = 0; s < OSTAGES - 1; s++)
        if (s < KT) load_stage(s, s);

    for (int kt = 0; kt < KT; kt++) {
        asm volatile("cp.async.wait_group %0;" :: "n"(OSTAGES - 2));
        __syncthreads();
        if (kt + OSTAGES - 1 < KT)
            load_stage((kt + OSTAGES - 1) % OSTAGES, kt + OSTAGES - 1);

        uint32_t sA = sbase + (kt % OSTAGES) * STAGE_BYTES;
        uint32_t sB = sA + A_ST_BYTES;
        const int krow = lane & 15;
#pragma unroll
        for (int ks = 0; ks < 4; ks++) {
            const int kcolb = (ks * 16 + (lane >> 4) * 8) * 2;
            uint32_t a[2][4], bb[4][4];
#pragma unroll
            for (int mt = 0; mt < 2; mt++)
                ldm_x4(sA + (wm * 32 + mt * 16 + krow) * ROWB + kcolb, a[mt]);
#pragma unroll
            for (int np = 0; np < 4; np++)
                ldm_x4(sB + (wn * 64 + np * 16 + krow) * ROWB + kcolb, bb[np]);
#pragma unroll
            for (int mt = 0; mt < 2; mt++)
#pragma unroll
                for (int nt = 0; nt < 8; nt++) {
                    uint32_t b0 = bb[nt >> 1][nt & 1];
                    uint32_t b1 = bb[nt >> 1][(nt & 1) + 2];
                    if (FP16M) {
                        mma_f16(acc[mt][nt], a[mt], b0, b1);
                    } else {
                        asm("mma.sync.aligned.m16n8k16.row.col.f32.bf16.bf16.f32 "
                            "{%0,%1,%2,%3}, {%4,%5,%6,%7}, {%8,%9}, {%0,%1,%2,%3};"
                            : "+f"(acc[mt][nt][0]), "+f"(acc[mt][nt][1]),
                              "+f"(acc[mt][nt][2]), "+f"(acc[mt][nt][3])
                            : "r"(a[mt][0]), "r"(a[mt][1]), "r"(a[mt][2]), "r"(a[mt][3]),
                              "r"(b0), "r"(b1));
                    }
                }
        }
    }

    const int row_b = m0 + wm * 32 + (lane >> 2);
    const int col_b = n0 + wn * 64 + (lane & 3) * 2;
#pragma unroll
    for (int nt = 0; nt < 8; nt++) {
        int col = col_b + nt * 8;
        float b0v = __ldg(bias + col);
        float b1v = __ldg(bias + col + 1);
#pragma unroll
        for (int mt = 0; mt < 2; mt++) {
            long long r0 = row_b + mt * 16;
            float2 v0 = make_float2(acc[mt][nt][0] + b0v, acc[mt][nt][1] + b1v);
            float2 v1 = make_float2(acc[mt][nt][2] + b0v, acc[mt][nt][3] + b1v);
            *(float2*)&C[r0 * N + col]       = v0;
            *(float2*)&C[(r0 + 8) * N + col] = v1;
        }
    }
}

// ---------------------------------------------------------------------------
// Persistent LSTM, HMMA matvec.
// CTA owns units [4c,4c+4) -> 16 gate-cols. Warp kg covers K slice
// [kg*64, kg*64+64) of each 512-wide segment (segs: hh*Whh | hl'*Whh | hh*Whl').
// z = accA + accB/2048. Partials reduced via sz as before.
// ---------------------------------------------------------------------------
__global__ void __launch_bounds__(256, 1)
lstm_persistent(const float* __restrict__ Wh, const float* __restrict__ cell,
                float* __restrict__ out) {
    extern __shared__ char smem[];
    float* sz = (float*)(smem + SZ_OFF);
    float* sc = (float*)(smem + SC_OFF);
    const uint32_t sbase = smem_u32(smem);
    const int tid = threadIdx.x;
    const int lane = tid & 31;
    const int kg = tid >> 5;           // warp id = K group
    const int u0 = blockIdx.x * 4;

    __shared__ unsigned s_gen0;
    if (tid == 0) s_gen0 = *(volatile unsigned*)&g_bar_gen;

    // one-time: Wh slice -> fp16 2-term in smem: swh[c][k]=Whh, swh[c][512+k]=Whl*2048
#pragma unroll
    for (int it = 0; it < 32; it++) {
        int e = tid + it * 256;        // 0..8191
        int k = e >> 4, c = e & 15;
        int uu = c >> 2, g = c & 3;
        float w = Wh[(long long)k * G4 + g * HH + u0 + uu];
        __half wh = __float2half(w);
        __half wl = __float2half((w - __half2float(wh)) * RSCALE);
        *(__half*)(smem + SWH_OFF + c * SWH_ROWB + k * 2)         = wh;
        *(__half*)(smem + SWH_OFF + c * SWH_ROWB + (512 + k) * 2) = wl;
    }
    if (tid < 128) sc[tid] = cell[(tid & 31) * HH + u0 + (tid >> 5)];
    __syncthreads();
    const unsigned gen0 = s_gen0;

    for (int t = 0; t < TT; t++) {
        const __half* __restrict__ srch = g_hh[t & 1];
        const __half* __restrict__ srcl = g_hl[t & 1];

        // warp loads its K slice of hh and hl': 32 rows x 64 halves each
#pragma unroll
        for (int j = 0; j < 8; j++) {
            int e = lane + j * 32;         // 0..255
            int b = e >> 3, ch = e & 7;
            cp_async16(sbase + SHH_OFF + b * SH_ROWB + kg * 128 + ch * 16,
                       srch + b * HH + kg * 64 + ch * 8);
            cp_async16(sbase + SHL_OFF + b * SH_ROWB + kg * 128 + ch * 16,
                       srcl + b * HH + kg * 64 + ch * 8);
        }
        asm volatile("cp.async.commit_group;" ::: "memory");
        asm volatile("cp.async.wait_group 0;" ::: "memory");
        __syncwarp();

        // HMMA: accA = hh*Whh ; accB = hl'*Whh + hh*Whl'
        float accA[2][2][4], accB[2][2][4];
#pragma unroll
        for (int i = 0; i < 2; i++)
#pragma unroll
            for (int j = 0; j < 2; j++)
#pragma unroll
                for (int q = 0; q < 4; q++) { accA[i][j][q] = 0.f; accB[i][j][q] = 0.f; }

        const int krow = lane & 15;
        const int kgrp = (lane >> 4) * 8;  // halves
#pragma unroll
        for (int seg = 0; seg < 3; seg++) {
            const uint32_t Abase = sbase + ((seg == 1) ? SHL_OFF : SHH_OFF);
            const uint32_t Bkoff = (seg == 2) ? 512u : 0u;
            float (*acc)[2][4] = (seg == 0) ? accA : accB;
#pragma unroll
            for (int ki = 0; ki < 4; ki++) {
                const int kcol = kg * 64 + ki * 16;
                uint32_t a[2][4], bb[4];
#pragma unroll
                for (int mt = 0; mt < 2; mt++)
                    ldm_x4(Abase + (mt * 16 + krow) * SH_ROWB + (kcol + kgrp) * 2, a[mt]);
                ldm_x4(sbase + SWH_OFF + krow * SWH_ROWB + (Bkoff + kcol + kgrp) * 2, bb);
#pragma unroll
                for (int mt = 0; mt < 2; mt++)
#pragma unroll
                    for (int nt = 0; nt < 2; nt++)
                        mma_f16(acc[mt][nt], a[mt], bb[nt], bb[nt + 2]);
            }
        }

        // partials -> sz[kg][c][b]
        {
            float* zb = sz + kg * 512;
#pragma unroll
            for (int mt = 0; mt < 2; mt++)
#pragma unroll
                for (int nt = 0; nt < 2; nt++)
#pragma unroll
                    for (int q = 0; q < 4; q++) {
                        int b = mt * 16 + (lane >> 2) + ((q >> 1) * 8);
                        int c = nt * 8 + (lane & 3) * 2 + (q & 1);
                        zb[c * 32 + b] = accA[mt][nt][q] + accB[mt][nt][q] * RINV;
                    }
        }
        __syncthreads();

        // reduce partials + nonlinearity (128 threads: 32 b x 4 units)
        if (tid < 128) {
            int bb = tid & 31, uu = tid >> 5;
            float z[4];
#pragma unroll
            for (int g = 0; g < 4; g++) {
                int c = uu * 4 + g;
                float s = 0.f;
#pragma unroll
                for (int q = 0; q < 8; q++) s += sz[q * 512 + c * 32 + bb];
                z[g] = s;
            }
            const float* xzr = g_xz + (long long)(bb * TT + t) * G4 + u0 + uu;
            float zi = z[0] + xzr[0 * HH];
            float zf = z[1] + xzr[1 * HH];
            float zg = z[2] + xzr[2 * HH];
            float zo = z[3] + xzr[3 * HH];
            float si = 1.f / (1.f + expf(-zi));
            float sf = 1.f / (1.f + expf(-zf));
            float so = 1.f / (1.f + expf(-zo));
            float cn = sf * sc[tid] + si * tanhf(zg);
            float hn = so * tanhf(cn);
            sc[tid] = cn;
            __half hh = __float2half(hn);
            __half hl = __float2half((hn - __half2float(hh)) * RSCALE);
            int hidx = bb * HH + u0 + uu;
            g_hh[(t + 1) & 1][hidx] = hh;
            g_hl[(t + 1) & 1][hidx] = hl;
            g_A[(long long)(bb * TT + t) * OKK + u0 + uu] = hh;
            if (t == TT - 1)
                out[LOGITS_ELEMS + hidx] = hn;
        }

        // grid barrier
        __syncthreads();
        if (tid == 0) {
            __threadfence();
            if (atomicAdd(&g_bar_cnt, 1u) == NCTA - 1) {
                *(volatile unsigned*)&g_bar_cnt = 0;
                __threadfence();
                atomicAdd(&g_bar_gen, 1u);
            } else {
                while (*(volatile unsigned*)&g_bar_gen - gen0 < (unsigned)(t + 1)) { }
            }
            __threadfence();
        }
        __syncthreads();
    }

    if (tid < 128) {
        out[LOGITS_ELEMS + BB * HH + (tid & 31) * HH + u0 + (tid >> 5)] = sc[tid];
    }
}

// ---------------------------------------------------------------------------
extern "C" void kernel_launch(void* const* d_in, const int* in_sizes, int n_in,
                              void* d_out, int out_size) {
    const int*   inputs = (const int*)  d_in[0];
    const float* hidden = (const float*)d_in[1];
    const float* cell   = (const float*)d_in[2];
    const float* emb    = (const float*)d_in[3];
    const float* Wx     = (const float*)d_in[4];
    const float* Wh     = (const float*)d_in[5];
    const float* bias   = (const float*)d_in[6];
    const float* Wout   = (const float*)d_in[7];
    const float* bout   = (const float*)d_in[8];
    float* out = (float*)d_out;

    float *pxz;
    __half *pA, *pB;
    __nv_bfloat16 *pA2, *pB2;
    cudaGetSymbolAddress((void**)&pxz, g_xz);
    cudaGetSymbolAddress((void**)&pA,  g_A);
    cudaGetSymbolAddress((void**)&pB,  g_B);
    cudaGetSymbolAddress((void**)&pA2, g_A2);
    cudaGetSymbolAddress((void**)&pB2, g_B2);

    cudaFuncSetAttribute(hmma_gemm<0>,
                         cudaFuncAttributeMaxDynamicSharedMemorySize, OSMEM);
    cudaFuncSetAttribute(hmma_gemm<1>,
                         cudaFuncAttributeMaxDynamicSharedMemorySize, OSMEM);
    cudaFuncSetAttribute(lstm_persistent,
                         cudaFuncAttributeMaxDynamicSharedMemorySize, L2SMEM);

    // 1. gather + split x -> A2 (bf16 3-term)
    split_x_kernel<<<(MM * XSEG + 255) / 256, 256>>>(inputs, emb);

    // 2. split + transpose W_x -> B2 (bf16 3-term)
    {
        dim3 grid(G4 / 32, XSEG / 32);   // (64, 10)
        split_wx_kernel<<<grid, dim3(32, 8)>>>(Wx);
    }

    // 3. init h (fp16 split pair)
    init_h_kernel<<<(BB * HH + 255) / 256, 256>>>(hidden);

    // 4. xz = A2 @ B2^T + b  (bf16 HMMA, 4096 x 2048 x 960)
    {
        dim3 grid(MM / OBM, G4 / OBN);   // (32, 16)
        hmma_gemm<0><<<grid, OTHREADS, OSMEM>>>((const uint16_t*)pA2,
                                                (const uint16_t*)pB2,
                                                bias, pxz, G4, XKK);
    }

    // 5. transpose W_out -> B (fp16)
    {
        dim3 grid(VV / 32, HH / 32);
        split_wout_kernel<<<grid, dim3(32, 8)>>>(Wout);
    }

    // 6. all 128 LSTM steps in ONE persistent launch (HMMA matvec)
    lstm_persistent<<<NCTA, 256, L2SMEM>>>(Wh, cell, out);

    // 7. logits = A @ B^T + b_out  (fp16 HMMA, 4096 x 32000 x 512)
    {
        dim3 grid(MM / OBM, VV / OBN);   // (32, 250)
        hmma_gemm<1><<<grid, OTHREADS, OSMEM>>>((const uint16_t*)pA,
                                                (const uint16_t*)pB,
                                                bout, out, VV, OKK);
    }
}